// round 1
// baseline (speedup 1.0000x reference)
#include <cuda_runtime.h>
#include <cuda_bf16.h>

// Shapes (fixed by the problem)
#define B_    8
#define CIN   64
#define HDIM  56
#define WDIM  56
#define HW    3136            // 56*56
#define NPX   25088           // B*H*W
#define NH    8
#define OCH   512             // per-projection output channels

// Scratch (allocation-free rule: __device__ globals)
__device__ float g_qkv[3ull * NPX * 512];        // [proj][px][oc] oc = n*64+c
__device__ float g_att[(unsigned long long)NPX * 512]; // [px][c'] c' = qc*8+n
__device__ float g_Wt[3 * 9 * 64 * 512];         // [proj][tap][ic][oc]
__device__ float g_Wut[512 * 64];                // [k][co]

// ---------------------------------------------------------------------------
// Weight transpose prep: Wt[((proj*9+tap)*64+ic)*512+oc] = Wsrc[(oc*64+ic)*9+tap]
//                        Wut[k*64+co] = Wu[co*512+k]
// ---------------------------------------------------------------------------
__global__ void prep_w(const float* __restrict__ Wq, const float* __restrict__ Wk,
                       const float* __restrict__ Wv, const float* __restrict__ Wu) {
    int idx = blockIdx.x * blockDim.x + threadIdx.x;
    const int tot = 3 * 9 * 64 * 512;
    if (idx < tot) {
        int oc = idx & 511;
        int t = idx >> 9;
        int ic = t & 63; t >>= 6;
        int tap = t % 9;
        int proj = t / 9;
        const float* src = (proj == 0) ? Wq : ((proj == 1) ? Wk : Wv);
        g_Wt[idx] = src[(oc * 64 + ic) * 9 + tap];
    }
    if (idx < 512 * 64) {
        int co = idx & 63;
        int k = idx >> 6;
        g_Wut[idx] = Wu[co * 512 + k];
    }
}

// ---------------------------------------------------------------------------
// Fused q/k/v 3x3 conv as implicit GEMM.
// grid.x = NPX/64 = 392 (pixel tiles), grid.y = 24 (proj*8 + oc-tile)
// Block computes C[64 px][64 oc] accumulating over 64 ic x 9 taps.
// Output layout: g_qkv[proj][px][oc] (pixel-major, contiguous per pixel).
// ---------------------------------------------------------------------------
__global__ __launch_bounds__(256) void conv_qkv(const float* __restrict__ x) {
    __shared__ float Ws[64][64];   // [ic][oc]
    __shared__ float Xs[64][64];   // [ic][px]

    const int tid = threadIdx.x;
    const int px0 = blockIdx.x * 64;
    const int octile = blockIdx.y;        // 0..23
    const int proj = octile >> 3;
    const int oc0 = (octile & 7) * 64;

    // 3136 % 64 == 0 -> whole tile is in one batch image
    const int b = px0 / HW;
    const int rem0 = px0 - b * HW;
    const int pl = tid & 63;              // this thread's pixel lane for X fills
    const int rem = rem0 + pl;
    const int h = rem / WDIM;
    const int w = rem - h * WDIM;
    const float* xb = x + (unsigned long long)b * CIN * HW;

    const int tx = tid & 15;              // oc quad
    const int ty = tid >> 4;              // px quad

    float acc[4][4];                      // [px_i][oc_j]
    #pragma unroll
    for (int i = 0; i < 4; i++)
        #pragma unroll
        for (int j = 0; j < 4; j++) acc[i][j] = 0.f;

    const float* wt = g_Wt + (unsigned long long)(proj * 9) * (64 * 512);

    for (int tap = 0; tap < 9; tap++) {
        const int dr = tap / 3 - 1;
        const int dc = tap % 3 - 1;

        // --- fill Ws (contiguous rows of 64 floats from pre-transposed weights)
        {
            const float* wsrc = wt + (unsigned long long)tap * (64 * 512) + oc0;
            #pragma unroll
            for (int i = 0; i < 4; i++) {
                int e4 = tid + i * 256;          // 0..1023 float4 slots
                int ic = e4 >> 4;
                int o4 = (e4 & 15) * 4;
                *(float4*)&Ws[ic][o4] = *(const float4*)(wsrc + ic * 512 + o4);
            }
        }
        // --- fill Xs (gather with zero-pad bounds)
        {
            const int hh = h + dr, ww = w + dc;
            const bool ok = (hh >= 0) & (hh < HDIM) & (ww >= 0) & (ww < WDIM);
            const int off = hh * WDIM + ww;
            #pragma unroll
            for (int i = 0; i < 16; i++) {
                int ic = (tid >> 6) + i * 4;     // 0..63
                Xs[ic][pl] = ok ? xb[ic * HW + off] : 0.f;
            }
        }
        __syncthreads();

        #pragma unroll 8
        for (int k = 0; k < 64; k++) {
            float4 a4 = *(const float4*)&Ws[k][tx * 4];
            float4 b4 = *(const float4*)&Xs[k][ty * 4];
            float av[4] = {a4.x, a4.y, a4.z, a4.w};
            float bv[4] = {b4.x, b4.y, b4.z, b4.w};
            #pragma unroll
            for (int i = 0; i < 4; i++)
                #pragma unroll
                for (int j = 0; j < 4; j++)
                    acc[i][j] += bv[i] * av[j];
        }
        __syncthreads();
    }

    float* outp = g_qkv + (unsigned long long)proj * NPX * 512;
    #pragma unroll
    for (int i = 0; i < 4; i++) {
        int px = px0 + ty * 4 + i;
        float4 v = make_float4(acc[i][0], acc[i][1], acc[i][2], acc[i][3]);
        *(float4*)(outp + (unsigned long long)px * 512 + oc0 + tx * 4) = v;
    }
}

// ---------------------------------------------------------------------------
// Per-pixel channel attention. 1 block = 1 pixel, 64 threads = query channels.
// Each thread owns a full softmax row -> no cross-thread reduction.
// Writes g_att[px][qc*8+n] (the order the 1x1 conv contracts).
// ---------------------------------------------------------------------------
__global__ __launch_bounds__(64) void attn_kernel() {
    const int p = blockIdx.x;
    const int tid = threadIdx.x;         // channel index
    const unsigned long long base = (unsigned long long)p * 512;
    const float* qp = g_qkv + base;
    const float* kp = g_qkv + (unsigned long long)NPX * 512 + base;
    const float* vp = g_qkv + 2ull * NPX * 512 + base;

    __shared__ float ks[8][64];
    __shared__ float vs[8][64];
    float qr[8];
    const float scale = 0.04419417382415922f;   // 1/sqrt(512)
    #pragma unroll
    for (int n = 0; n < 8; n++) {
        ks[n][tid] = kp[n * 64 + tid];
        vs[n][tid] = vp[n * 64 + tid];
        qr[n] = qp[n * 64 + tid] * scale;
    }
    __syncthreads();

    float s[64];
    float m = -1e30f;
    #pragma unroll 4
    for (int kk = 0; kk < 64; kk++) {
        float a = 0.f;
        #pragma unroll
        for (int n = 0; n < 8; n++) a += qr[n] * ks[n][kk];
        s[kk] = a;
        m = fmaxf(m, a);
    }
    float sum = 0.f;
    #pragma unroll 4
    for (int kk = 0; kk < 64; kk++) {
        float e = __expf(s[kk] - m);
        s[kk] = e;
        sum += e;
    }
    const float inv = 1.0f / sum;

    float a[8] = {0.f, 0.f, 0.f, 0.f, 0.f, 0.f, 0.f, 0.f};
    #pragma unroll 4
    for (int kk = 0; kk < 64; kk++) {
        float pexp = s[kk];
        #pragma unroll
        for (int n = 0; n < 8; n++) a[n] += pexp * vs[n][kk];
    }

    float* ap = g_att + base + tid * 8;   // c' = tid*8 + n
    float4 v0 = make_float4(a[0] * inv, a[1] * inv, a[2] * inv, a[3] * inv);
    float4 v1 = make_float4(a[4] * inv, a[5] * inv, a[6] * inv, a[7] * inv);
    *(float4*)(ap + 0) = v0;
    *(float4*)(ap + 4) = v1;
}

// ---------------------------------------------------------------------------
// 1x1 conv (Wu) + ReLU as GEMM: out[64 co][NPX px] = Wut[512][64]^T @ att
// grid = 392 pixel tiles; BM=64(co) x BN=64(px) x K=512.
// ---------------------------------------------------------------------------
__global__ __launch_bounds__(256) void wu_gemm(float* __restrict__ out) {
    __shared__ float Wus[64][64];   // [k][co]
    __shared__ float As[64][65];    // [k][px], pad 65 to break conflicts

    const int tid = threadIdx.x;
    const int px0 = blockIdx.x * 64;
    const int tx = tid & 15;        // px quad
    const int ty = tid >> 4;        // co quad

    float acc[4][4];                // [co_i][px_j]
    #pragma unroll
    for (int i = 0; i < 4; i++)
        #pragma unroll
        for (int j = 0; j < 4; j++) acc[i][j] = 0.f;

    for (int k0 = 0; k0 < 512; k0 += 64) {
        // Wus: contiguous 16KB copy
        {
            const float4* src = (const float4*)(g_Wut + k0 * 64);
            float4* dst = (float4*)&Wus[0][0];
            #pragma unroll
            for (int i = 0; i < 4; i++) dst[tid + i * 256] = src[tid + i * 256];
        }
        // As: transposed fill from att[px][512]
        #pragma unroll
        for (int i = 0; i < 4; i++) {
            int e4 = tid + i * 256;           // 0..1023
            int plf = e4 >> 4;                // px lane 0..63
            int k4 = (e4 & 15) * 4;
            float4 v = *(const float4*)(g_att + (unsigned long long)(px0 + plf) * 512 + k0 + k4);
            As[k4 + 0][plf] = v.x;
            As[k4 + 1][plf] = v.y;
            As[k4 + 2][plf] = v.z;
            As[k4 + 3][plf] = v.w;
        }
        __syncthreads();

        #pragma unroll 8
        for (int k = 0; k < 64; k++) {
            float4 a4 = *(const float4*)&Wus[k][ty * 4];
            float av[4] = {a4.x, a4.y, a4.z, a4.w};
            float bv[4];
            #pragma unroll
            for (int j = 0; j < 4; j++) bv[j] = As[k][tx * 4 + j];
            #pragma unroll
            for (int i = 0; i < 4; i++)
                #pragma unroll
                for (int j = 0; j < 4; j++)
                    acc[i][j] += av[i] * bv[j];
        }
        __syncthreads();
    }

    // out is [B][64][56][56]; px tile stays within one image (3136 % 64 == 0)
    const int b = px0 / HW;
    const int hw0 = px0 - b * HW + tx * 4;
    #pragma unroll
    for (int i = 0; i < 4; i++) {
        int co = ty * 4 + i;
        float4 v = make_float4(fmaxf(acc[i][0], 0.f), fmaxf(acc[i][1], 0.f),
                               fmaxf(acc[i][2], 0.f), fmaxf(acc[i][3], 0.f));
        *(float4*)(out + ((unsigned long long)(b * 64 + co)) * HW + hw0) = v;
    }
}

// ---------------------------------------------------------------------------
extern "C" void kernel_launch(void* const* d_in, const int* in_sizes, int n_in,
                              void* d_out, int out_size) {
    const float* x  = (const float*)d_in[0];
    const float* Wq = (const float*)d_in[1];
    const float* Wk = (const float*)d_in[2];
    const float* Wv = (const float*)d_in[3];
    const float* Wu = (const float*)d_in[4];
    float* out = (float*)d_out;

    // 1) weight transposes
    prep_w<<<(3 * 9 * 64 * 512 + 255) / 256, 256>>>(Wq, Wk, Wv, Wu);
    // 2) fused qkv 3x3 conv
    conv_qkv<<<dim3(NPX / 64, 24), 256>>>(x);
    // 3) per-pixel attention
    attn_kernel<<<NPX, 64>>>();
    // 4) 1x1 conv + relu
    wu_gemm<<<NPX / 64, 256>>>(out);
}

// round 2
// speedup vs baseline: 4.5403x; 4.5403x over previous
#include <cuda_runtime.h>
#include <cuda_bf16.h>
#include <cstdint>

// Shapes (fixed by the problem)
#define B_    8
#define CIN   64
#define HDIM  56
#define WDIM  56
#define HW    3136
#define NPX   25088           // B*H*W
#define KTOT  576             // 9 taps * 64 ic

// Scratch (__device__ globals; no allocation allowed)
__device__ float g_qkv[3ull * NPX * 512];               // [proj][px][oc]
__device__ float g_att[(unsigned long long)NPX * 512];  // [px][qc*8+n]
__device__ float g_col[(unsigned long long)KTOT * NPX]; // [k][px]  (tf32-rounded)
__device__ float g_Wt[3 * 9 * 64 * 512];                // [proj][tap][ic][oc] (tf32-rounded)
__device__ float g_Wut[512 * 64];                       // [k][co] fp32

__device__ __forceinline__ float to_tf32(float x) {
    unsigned u;
    asm("cvt.rna.tf32.f32 %0, %1;" : "=r"(u) : "f"(x));
    return __uint_as_float(u);
}

// ---------------------------------------------------------------------------
// Weight prep: transpose + tf32 rounding for the conv weights.
// ---------------------------------------------------------------------------
__global__ void prep_w(const float* __restrict__ Wq, const float* __restrict__ Wk,
                       const float* __restrict__ Wv, const float* __restrict__ Wu) {
    int idx = blockIdx.x * blockDim.x + threadIdx.x;
    const int tot = 3 * 9 * 64 * 512;
    if (idx < tot) {
        int oc = idx & 511;
        int t = idx >> 9;
        int ic = t & 63; t >>= 6;
        int tap = t % 9;
        int proj = t / 9;
        const float* src = (proj == 0) ? Wq : ((proj == 1) ? Wk : Wv);
        g_Wt[idx] = to_tf32(src[(oc * 64 + ic) * 9 + tap]);
    }
    if (idx < 512 * 64) {
        int co = idx & 63;
        int k = idx >> 6;
        g_Wut[idx] = Wu[co * 512 + k];
    }
}

// ---------------------------------------------------------------------------
// im2col with zero pad, tf32-rounded: g_col[k][px], k = tap*64+ic
// ---------------------------------------------------------------------------
__global__ __launch_bounds__(256) void im2col(const float* __restrict__ x) {
    const int px = blockIdx.x * 256 + threadIdx.x;
    const int k = blockIdx.y;            // 0..575
    const int tap = k >> 6;
    const int ic = k & 63;
    const int dr = tap / 3 - 1;
    const int dc = tap % 3 - 1;
    const int b = px / HW;
    const int rem = px - b * HW;
    const int h = rem / WDIM;
    const int w = rem - h * WDIM;
    const int hh = h + dr, ww = w + dc;
    float v = 0.f;
    if (hh >= 0 && hh < HDIM && ww >= 0 && ww < WDIM)
        v = x[((size_t)(b * CIN + ic)) * HW + hh * WDIM + ww];
    g_col[(size_t)k * NPX + px] = to_tf32(v);
}

// ---------------------------------------------------------------------------
// q/k/v conv as tf32 tensor-core GEMM: C[px][oc] = g_col^T @ W
// BM=128, BN=128, BK=32, 128 threads (4 warps, 2x2), warp tile 64x64.
// Smem [k][m] rows with stride 136 (==8 mod 32) -> conflict-free frag loads.
// grid = (196 px-tiles, 4 oc-tiles, 3 proj)
// ---------------------------------------------------------------------------
#define BM 128
#define BN 128
#define BKc 32
#define SSTR 136

__device__ __forceinline__ void cp_async16(void* smem, const void* gmem) {
    unsigned saddr = (unsigned)__cvta_generic_to_shared(smem);
    asm volatile("cp.async.cg.shared.global [%0], [%1], 16;" :: "r"(saddr), "l"(gmem));
}

__global__ __launch_bounds__(128, 2) void conv_mma() {
    __shared__ float As[BKc][SSTR];   // [k][m]
    __shared__ float Bs[BKc][SSTR];   // [k][n]

    const int tid = threadIdx.x;
    const int warp = tid >> 5;
    const int lane = tid & 31;
    const int g = lane >> 2;          // group id 0..7
    const int t = lane & 3;           // thread in group 0..3

    const int px0 = blockIdx.x * BM;
    const int oc0 = blockIdx.y * BN;
    const int proj = blockIdx.z;

    const int warpM = (warp & 1) * 64;
    const int warpN = (warp >> 1) * 64;

    const float* wsrc = g_Wt + (size_t)proj * (KTOT * 512);

    float acc[4][8][4];
    #pragma unroll
    for (int mt = 0; mt < 4; mt++)
        #pragma unroll
        for (int nt = 0; nt < 8; nt++)
            #pragma unroll
            for (int r = 0; r < 4; r++) acc[mt][nt][r] = 0.f;

    for (int k0 = 0; k0 < KTOT; k0 += BKc) {
        __syncthreads();   // prior iter done reading smem
        // fill A and B tiles: 1024 float4 each, 8 per thread
        #pragma unroll
        for (int i = 0; i < 8; i++) {
            int idx = i * 128 + tid;          // 0..1023
            int row = idx >> 5;
            int col = (idx & 31) << 2;
            cp_async16(&As[row][col], g_col + (size_t)(k0 + row) * NPX + px0 + col);
            cp_async16(&Bs[row][col], wsrc + (size_t)(k0 + row) * 512 + oc0 + col);
        }
        asm volatile("cp.async.commit_group;");
        asm volatile("cp.async.wait_group 0;");
        __syncthreads();

        #pragma unroll
        for (int ks = 0; ks < 4; ks++) {
            const int kb = ks * 8;
            float af[4][4];
            #pragma unroll
            for (int mt = 0; mt < 4; mt++) {
                int m = warpM + mt * 16 + g;
                af[mt][0] = As[kb + t][m];
                af[mt][1] = As[kb + t][m + 8];
                af[mt][2] = As[kb + t + 4][m];
                af[mt][3] = As[kb + t + 4][m + 8];
            }
            float bf[8][2];
            #pragma unroll
            for (int nt = 0; nt < 8; nt++) {
                int n = warpN + nt * 8 + g;
                bf[nt][0] = Bs[kb + t][n];
                bf[nt][1] = Bs[kb + t + 4][n];
            }
            #pragma unroll
            for (int mt = 0; mt < 4; mt++) {
                #pragma unroll
                for (int nt = 0; nt < 8; nt++) {
                    asm volatile(
                        "mma.sync.aligned.m16n8k8.row.col.f32.tf32.tf32.f32 "
                        "{%0,%1,%2,%3}, {%4,%5,%6,%7}, {%8,%9}, {%0,%1,%2,%3};"
                        : "+f"(acc[mt][nt][0]), "+f"(acc[mt][nt][1]),
                          "+f"(acc[mt][nt][2]), "+f"(acc[mt][nt][3])
                        : "r"(__float_as_uint(af[mt][0])), "r"(__float_as_uint(af[mt][1])),
                          "r"(__float_as_uint(af[mt][2])), "r"(__float_as_uint(af[mt][3])),
                          "r"(__float_as_uint(bf[nt][0])), "r"(__float_as_uint(bf[nt][1])));
                }
            }
        }
    }

    float* outp = g_qkv + (size_t)proj * NPX * 512;
    #pragma unroll
    for (int mt = 0; mt < 4; mt++) {
        #pragma unroll
        for (int nt = 0; nt < 8; nt++) {
            int r0 = px0 + warpM + mt * 16 + g;
            int c0 = oc0 + warpN + nt * 8 + 2 * t;
            float2 v01 = make_float2(acc[mt][nt][0], acc[mt][nt][1]);
            float2 v23 = make_float2(acc[mt][nt][2], acc[mt][nt][3]);
            *(float2*)(outp + (size_t)r0 * 512 + c0) = v01;
            *(float2*)(outp + (size_t)(r0 + 8) * 512 + c0) = v23;
        }
    }
}

// ---------------------------------------------------------------------------
// Per-pixel channel attention; 4 pixels per block, 64 threads each.
// Fully unrolled so s[64] stays in registers.
// ---------------------------------------------------------------------------
__global__ __launch_bounds__(256) void attn_kernel() {
    const int sp = threadIdx.x >> 6;
    const int tid = threadIdx.x & 63;
    const int p = blockIdx.x * 4 + sp;
    const size_t base = (size_t)p * 512;
    const float* qp = g_qkv + base;
    const float* kp = g_qkv + (size_t)NPX * 512 + base;
    const float* vp = g_qkv + 2ull * NPX * 512 + base;

    __shared__ float ks[4][8][64];
    __shared__ float vs[4][8][64];
    float qr[8];
    const float scale = 0.04419417382415922f;   // 1/sqrt(512)
    #pragma unroll
    for (int n = 0; n < 8; n++) {
        ks[sp][n][tid] = kp[n * 64 + tid];
        vs[sp][n][tid] = vp[n * 64 + tid];
        qr[n] = qp[n * 64 + tid] * scale;
    }
    __syncthreads();

    float s[64];
    float m = -1e30f;
    #pragma unroll
    for (int kk = 0; kk < 64; kk++) {
        float a = 0.f;
        #pragma unroll
        for (int n = 0; n < 8; n++) a += qr[n] * ks[sp][n][kk];
        s[kk] = a;
        m = fmaxf(m, a);
    }
    float sum = 0.f;
    #pragma unroll
    for (int kk = 0; kk < 64; kk++) {
        float e = __expf(s[kk] - m);
        s[kk] = e;
        sum += e;
    }
    const float inv = 1.0f / sum;

    float a[8] = {0.f, 0.f, 0.f, 0.f, 0.f, 0.f, 0.f, 0.f};
    #pragma unroll
    for (int kk = 0; kk < 64; kk++) {
        float pe = s[kk];
        #pragma unroll
        for (int n = 0; n < 8; n++) a[n] += pe * vs[sp][n][kk];
    }

    float* ap = g_att + base + tid * 8;   // c' = qc*8 + n
    *(float4*)(ap + 0) = make_float4(a[0] * inv, a[1] * inv, a[2] * inv, a[3] * inv);
    *(float4*)(ap + 4) = make_float4(a[4] * inv, a[5] * inv, a[6] * inv, a[7] * inv);
}

// ---------------------------------------------------------------------------
// 1x1 conv (Wu) + ReLU, fp32 SIMT (kept for accuracy margin).
// ---------------------------------------------------------------------------
__global__ __launch_bounds__(256) void wu_gemm(float* __restrict__ out) {
    __shared__ float Wus[64][64];   // [k][co]
    __shared__ float As[64][65];    // [k][px]

    const int tid = threadIdx.x;
    const int px0 = blockIdx.x * 64;
    const int tx = tid & 15;        // px quad
    const int ty = tid >> 4;        // co quad

    float acc[4][4];
    #pragma unroll
    for (int i = 0; i < 4; i++)
        #pragma unroll
        for (int j = 0; j < 4; j++) acc[i][j] = 0.f;

    for (int k0 = 0; k0 < 512; k0 += 64) {
        {
            const float4* src = (const float4*)(g_Wut + k0 * 64);
            float4* dst = (float4*)&Wus[0][0];
            #pragma unroll
            for (int i = 0; i < 4; i++) dst[tid + i * 256] = src[tid + i * 256];
        }
        #pragma unroll
        for (int i = 0; i < 4; i++) {
            int e4 = tid + i * 256;
            int plf = e4 >> 4;
            int k4 = (e4 & 15) * 4;
            float4 v = *(const float4*)(g_att + (size_t)(px0 + plf) * 512 + k0 + k4);
            As[k4 + 0][plf] = v.x;
            As[k4 + 1][plf] = v.y;
            As[k4 + 2][plf] = v.z;
            As[k4 + 3][plf] = v.w;
        }
        __syncthreads();

        #pragma unroll 8
        for (int k = 0; k < 64; k++) {
            float4 a4 = *(const float4*)&Wus[k][ty * 4];
            float av[4] = {a4.x, a4.y, a4.z, a4.w};
            float bv[4];
            #pragma unroll
            for (int j = 0; j < 4; j++) bv[j] = As[k][tx * 4 + j];
            #pragma unroll
            for (int i = 0; i < 4; i++)
                #pragma unroll
                for (int j = 0; j < 4; j++)
                    acc[i][j] += av[i] * bv[j];
        }
        __syncthreads();
    }

    const int b = px0 / HW;
    const int hw0 = px0 - b * HW + tx * 4;
    #pragma unroll
    for (int i = 0; i < 4; i++) {
        int co = ty * 4 + i;
        float4 v = make_float4(fmaxf(acc[i][0], 0.f), fmaxf(acc[i][1], 0.f),
                               fmaxf(acc[i][2], 0.f), fmaxf(acc[i][3], 0.f));
        *(float4*)(out + ((size_t)(b * 64 + co)) * HW + hw0) = v;
    }
}

// ---------------------------------------------------------------------------
extern "C" void kernel_launch(void* const* d_in, const int* in_sizes, int n_in,
                              void* d_out, int out_size) {
    const float* x  = (const float*)d_in[0];
    const float* Wq = (const float*)d_in[1];
    const float* Wk = (const float*)d_in[2];
    const float* Wv = (const float*)d_in[3];
    const float* Wu = (const float*)d_in[4];
    float* out = (float*)d_out;

    prep_w<<<(3 * 9 * 64 * 512 + 255) / 256, 256>>>(Wq, Wk, Wv, Wu);
    im2col<<<dim3(NPX / 256, KTOT), 256>>>(x);
    conv_mma<<<dim3(NPX / BM, 512 / BN, 3), 128>>>();
    attn_kernel<<<NPX / 4, 256>>>();
    wu_gemm<<<NPX / 64, 256>>>(out);
}

// round 3
// speedup vs baseline: 4.8041x; 1.0581x over previous
#include <cuda_runtime.h>
#include <cuda_bf16.h>
#include <cstdint>

#define B_    8
#define CIN   64
#define HDIM  56
#define WDIM  56
#define HW    3136
#define NPX   25088
#define KTOT  576

__device__ float g_qkv[3ull * NPX * 512];
__device__ float g_att[(unsigned long long)NPX * 512];   // [px][qc*8+n] tf32
__device__ float g_col[(unsigned long long)KTOT * NPX];  // [k][px] tf32
__device__ float g_Wt[3 * 9 * 64 * 512];                 // [proj][tap][ic][oc] tf32
__device__ float g_Wut[512 * 64];                        // [k][co] tf32

__device__ __forceinline__ float to_tf32(float x) {
    unsigned u;
    asm("cvt.rna.tf32.f32 %0, %1;" : "=r"(u) : "f"(x));
    return __uint_as_float(u);
}

__device__ __forceinline__ void cp_async16(void* smem, const void* gmem) {
    unsigned saddr = (unsigned)__cvta_generic_to_shared(smem);
    asm volatile("cp.async.cg.shared.global [%0], [%1], 16;" :: "r"(saddr), "l"(gmem));
}
__device__ __forceinline__ void cp_commit() { asm volatile("cp.async.commit_group;"); }
__device__ __forceinline__ void cp_wait0() { asm volatile("cp.async.wait_group 0;"); }

// ---------------------------------------------------------------------------
__global__ void prep_w(const float* __restrict__ Wq, const float* __restrict__ Wk,
                       const float* __restrict__ Wv, const float* __restrict__ Wu) {
    int idx = blockIdx.x * blockDim.x + threadIdx.x;
    const int tot = 3 * 9 * 64 * 512;
    if (idx < tot) {
        int oc = idx & 511;
        int t = idx >> 9;
        int ic = t & 63; t >>= 6;
        int tap = t % 9;
        int proj = t / 9;
        const float* src = (proj == 0) ? Wq : ((proj == 1) ? Wk : Wv);
        g_Wt[idx] = to_tf32(src[(oc * 64 + ic) * 9 + tap]);
    }
    if (idx < 512 * 64) {
        int co = idx & 63;
        int k = idx >> 6;
        g_Wut[idx] = to_tf32(Wu[co * 512 + k]);
    }
}

// ---------------------------------------------------------------------------
__global__ __launch_bounds__(256) void im2col(const float* __restrict__ x) {
    const int px = blockIdx.x * 256 + threadIdx.x;
    const int k = blockIdx.y;
    const int tap = k >> 6;
    const int ic = k & 63;
    const int dr = tap / 3 - 1;
    const int dc = tap % 3 - 1;
    const int b = px / HW;
    const int rem = px - b * HW;
    const int h = rem / WDIM;
    const int w = rem - h * WDIM;
    const int hh = h + dr, ww = w + dc;
    float v = 0.f;
    if (hh >= 0 && hh < HDIM && ww >= 0 && ww < WDIM)
        v = x[((size_t)(b * CIN + ic)) * HW + hh * WDIM + ww];
    g_col[(size_t)k * NPX + px] = to_tf32(v);
}

// ---------------------------------------------------------------------------
// qkv conv GEMM, tf32 mma, 2-stage cp.async pipeline. BM=128 BN=128 BK=16.
// ---------------------------------------------------------------------------
#define BM 128
#define BN 128
#define BKc 16
#define SSTR 136

__global__ __launch_bounds__(128, 2) void conv_mma() {
    __shared__ float As[2][BKc][SSTR];   // [k][m(px)]
    __shared__ float Bs[2][BKc][SSTR];   // [k][n(oc)]

    const int tid = threadIdx.x;
    const int warp = tid >> 5;
    const int lane = tid & 31;
    const int g = lane >> 2;
    const int t = lane & 3;

    const int px0 = blockIdx.x * BM;
    const int oc0 = blockIdx.y * BN;
    const int proj = blockIdx.z;
    const int warpM = (warp & 1) * 64;
    const int warpN = (warp >> 1) * 64;

    const float* wsrc = g_Wt + (size_t)proj * (KTOT * 512);

    float acc[4][8][4];
    #pragma unroll
    for (int mt = 0; mt < 4; mt++)
        #pragma unroll
        for (int nt = 0; nt < 8; nt++)
            #pragma unroll
            for (int r = 0; r < 4; r++) acc[mt][nt][r] = 0.f;

    // prologue: stage 0
    #pragma unroll
    for (int i = 0; i < 4; i++) {
        int idx = i * 128 + tid;
        int row = idx >> 5;
        int col = (idx & 31) << 2;
        cp_async16(&As[0][row][col], g_col + (size_t)row * NPX + px0 + col);
        cp_async16(&Bs[0][row][col], wsrc + (size_t)row * 512 + oc0 + col);
    }
    cp_commit();

    int buf = 0;
    for (int k0 = 0; k0 < KTOT; k0 += BKc) {
        cp_wait0();
        __syncthreads();

        const int kn = k0 + BKc;
        if (kn < KTOT) {
            const int nb = buf ^ 1;
            #pragma unroll
            for (int i = 0; i < 4; i++) {
                int idx = i * 128 + tid;
                int row = idx >> 5;
                int col = (idx & 31) << 2;
                cp_async16(&As[nb][row][col], g_col + (size_t)(kn + row) * NPX + px0 + col);
                cp_async16(&Bs[nb][row][col], wsrc + (size_t)(kn + row) * 512 + oc0 + col);
            }
            cp_commit();
        }

        #pragma unroll
        for (int ks = 0; ks < 2; ks++) {
            const int kb = ks * 8;
            float af[4][4];
            #pragma unroll
            for (int mt = 0; mt < 4; mt++) {
                int m = warpM + mt * 16 + g;
                af[mt][0] = As[buf][kb + t][m];
                af[mt][1] = As[buf][kb + t][m + 8];
                af[mt][2] = As[buf][kb + t + 4][m];
                af[mt][3] = As[buf][kb + t + 4][m + 8];
            }
            float bf[8][2];
            #pragma unroll
            for (int nt = 0; nt < 8; nt++) {
                int n = warpN + nt * 8 + g;
                bf[nt][0] = Bs[buf][kb + t][n];
                bf[nt][1] = Bs[buf][kb + t + 4][n];
            }
            #pragma unroll
            for (int mt = 0; mt < 4; mt++) {
                #pragma unroll
                for (int nt = 0; nt < 8; nt++) {
                    asm volatile(
                        "mma.sync.aligned.m16n8k8.row.col.f32.tf32.tf32.f32 "
                        "{%0,%1,%2,%3}, {%4,%5,%6,%7}, {%8,%9}, {%0,%1,%2,%3};"
                        : "+f"(acc[mt][nt][0]), "+f"(acc[mt][nt][1]),
                          "+f"(acc[mt][nt][2]), "+f"(acc[mt][nt][3])
                        : "r"(__float_as_uint(af[mt][0])), "r"(__float_as_uint(af[mt][1])),
                          "r"(__float_as_uint(af[mt][2])), "r"(__float_as_uint(af[mt][3])),
                          "r"(__float_as_uint(bf[nt][0])), "r"(__float_as_uint(bf[nt][1])));
                }
            }
        }
        buf ^= 1;
    }

    float* outp = g_qkv + (size_t)proj * NPX * 512;
    #pragma unroll
    for (int mt = 0; mt < 4; mt++) {
        #pragma unroll
        for (int nt = 0; nt < 8; nt++) {
            int r0 = px0 + warpM + mt * 16 + g;
            int c0 = oc0 + warpN + nt * 8 + 2 * t;
            *(float2*)(outp + (size_t)r0 * 512 + c0) = make_float2(acc[mt][nt][0], acc[mt][nt][1]);
            *(float2*)(outp + (size_t)(r0 + 8) * 512 + c0) = make_float2(acc[mt][nt][2], acc[mt][nt][3]);
        }
    }
}

// ---------------------------------------------------------------------------
// Per-pixel channel attention; 4 px/block; vectorized smem reads (LDS.128).
// Writes att tf32-rounded for the tf32 wu GEMM.
// ---------------------------------------------------------------------------
__global__ __launch_bounds__(256) void attn_kernel() {
    const int sp = threadIdx.x >> 6;
    const int tid = threadIdx.x & 63;
    const int p = blockIdx.x * 4 + sp;
    const size_t base = (size_t)p * 512;
    const float* qp = g_qkv + base;
    const float* kp = g_qkv + (size_t)NPX * 512 + base;
    const float* vp = g_qkv + 2ull * NPX * 512 + base;

    __shared__ float ks[4][8][64];
    __shared__ float vs[4][8][64];
    float qr[8];
    const float scale = 0.04419417382415922f;   // 1/sqrt(512)
    #pragma unroll
    for (int n = 0; n < 8; n++) {
        ks[sp][n][tid] = kp[n * 64 + tid];
        vs[sp][n][tid] = vp[n * 64 + tid];
        qr[n] = qp[n * 64 + tid] * scale;
    }
    __syncthreads();

    float s[64];
    float m = -1e30f;
    #pragma unroll
    for (int kk = 0; kk < 64; kk += 4) {
        float4 a4 = make_float4(0.f, 0.f, 0.f, 0.f);
        #pragma unroll
        for (int n = 0; n < 8; n++) {
            float4 kv = *(const float4*)&ks[sp][n][kk];
            a4.x += qr[n] * kv.x;
            a4.y += qr[n] * kv.y;
            a4.z += qr[n] * kv.z;
            a4.w += qr[n] * kv.w;
        }
        s[kk] = a4.x; s[kk + 1] = a4.y; s[kk + 2] = a4.z; s[kk + 3] = a4.w;
        m = fmaxf(m, fmaxf(fmaxf(a4.x, a4.y), fmaxf(a4.z, a4.w)));
    }
    float sum = 0.f;
    #pragma unroll
    for (int kk = 0; kk < 64; kk++) {
        float e = __expf(s[kk] - m);
        s[kk] = e;
        sum += e;
    }
    const float inv = 1.0f / sum;

    float a[8] = {0.f, 0.f, 0.f, 0.f, 0.f, 0.f, 0.f, 0.f};
    #pragma unroll
    for (int kk = 0; kk < 64; kk += 4) {
        #pragma unroll
        for (int n = 0; n < 8; n++) {
            float4 vv = *(const float4*)&vs[sp][n][kk];
            a[n] += s[kk] * vv.x + s[kk + 1] * vv.y + s[kk + 2] * vv.z + s[kk + 3] * vv.w;
        }
    }

    float* ap = g_att + base + tid * 8;
    *(float4*)(ap + 0) = make_float4(to_tf32(a[0] * inv), to_tf32(a[1] * inv),
                                     to_tf32(a[2] * inv), to_tf32(a[3] * inv));
    *(float4*)(ap + 4) = make_float4(to_tf32(a[4] * inv), to_tf32(a[5] * inv),
                                     to_tf32(a[6] * inv), to_tf32(a[7] * inv));
}

// ---------------------------------------------------------------------------
// 1x1 conv (Wu) + ReLU as tf32 MMA GEMM. M=px(64 tile), N=co(64), K=512.
// 128 thr; warps 2(M)x2(N); warp tile 32x32. Double-buffered.
// ---------------------------------------------------------------------------
#define WUS 72

__global__ __launch_bounds__(128) void wu_mma(float* __restrict__ out) {
    __shared__ float Ats[2][32][WUS];   // [k][px]
    __shared__ float Ws[2][32][WUS];    // [k][co]

    const int tid = threadIdx.x;
    const int warp = tid >> 5;
    const int lane = tid & 31;
    const int g = lane >> 2;
    const int t = lane & 3;

    const int px0 = blockIdx.x * 64;
    const int warpM = (warp & 1) * 32;
    const int warpN = (warp >> 1) * 32;

    float acc[2][4][4];
    #pragma unroll
    for (int mt = 0; mt < 2; mt++)
        #pragma unroll
        for (int nt = 0; nt < 4; nt++)
            #pragma unroll
            for (int r = 0; r < 4; r++) acc[mt][nt][r] = 0.f;

    // ---- fill stage 0
    {
        if (tid < 64) {
            const float* src = g_att + (size_t)(px0 + tid) * 512;
            #pragma unroll
            for (int j = 0; j < 8; j++) {
                float4 v = *(const float4*)(src + j * 4);
                Ats[0][j * 4 + 0][tid] = v.x;
                Ats[0][j * 4 + 1][tid] = v.y;
                Ats[0][j * 4 + 2][tid] = v.z;
                Ats[0][j * 4 + 3][tid] = v.w;
            }
        } else {
            int t2 = tid - 64;
            #pragma unroll
            for (int i = 0; i < 8; i++) {
                int idx = t2 + i * 64;
                int row = idx >> 4;
                int col = (idx & 15) * 4;
                cp_async16(&Ws[0][row][col], g_Wut + row * 64 + col);
            }
        }
        cp_commit();
    }

    int buf = 0;
    for (int k0 = 0; k0 < 512; k0 += 32) {
        cp_wait0();
        __syncthreads();

        const int kn = k0 + 32;
        if (kn < 512) {
            const int nb = buf ^ 1;
            if (tid < 64) {
                const float* src = g_att + (size_t)(px0 + tid) * 512 + kn;
                #pragma unroll
                for (int j = 0; j < 8; j++) {
                    float4 v = *(const float4*)(src + j * 4);
                    Ats[nb][j * 4 + 0][tid] = v.x;
                    Ats[nb][j * 4 + 1][tid] = v.y;
                    Ats[nb][j * 4 + 2][tid] = v.z;
                    Ats[nb][j * 4 + 3][tid] = v.w;
                }
            } else {
                int t2 = tid - 64;
                #pragma unroll
                for (int i = 0; i < 8; i++) {
                    int idx = t2 + i * 64;
                    int row = idx >> 4;
                    int col = (idx & 15) * 4;
                    cp_async16(&Ws[nb][row][col], g_Wut + (kn + row) * 64 + col);
                }
            }
            cp_commit();
        }

        #pragma unroll
        for (int ks = 0; ks < 4; ks++) {
            const int kb = ks * 8;
            float af[2][4];
            #pragma unroll
            for (int mt = 0; mt < 2; mt++) {
                int mm = warpM + mt * 16 + g;
                af[mt][0] = Ats[buf][kb + t][mm];
                af[mt][1] = Ats[buf][kb + t][mm + 8];
                af[mt][2] = Ats[buf][kb + t + 4][mm];
                af[mt][3] = Ats[buf][kb + t + 4][mm + 8];
            }
            float bf[4][2];
            #pragma unroll
            for (int nt = 0; nt < 4; nt++) {
                int n = warpN + nt * 8 + g;
                bf[nt][0] = Ws[buf][kb + t][n];
                bf[nt][1] = Ws[buf][kb + t + 4][n];
            }
            #pragma unroll
            for (int mt = 0; mt < 2; mt++) {
                #pragma unroll
                for (int nt = 0; nt < 4; nt++) {
                    asm volatile(
                        "mma.sync.aligned.m16n8k8.row.col.f32.tf32.tf32.f32 "
                        "{%0,%1,%2,%3}, {%4,%5,%6,%7}, {%8,%9}, {%0,%1,%2,%3};"
                        : "+f"(acc[mt][nt][0]), "+f"(acc[mt][nt][1]),
                          "+f"(acc[mt][nt][2]), "+f"(acc[mt][nt][3])
                        : "r"(__float_as_uint(af[mt][0])), "r"(__float_as_uint(af[mt][1])),
                          "r"(__float_as_uint(af[mt][2])), "r"(__float_as_uint(af[mt][3])),
                          "r"(__float_as_uint(bf[nt][0])), "r"(__float_as_uint(bf[nt][1])));
                }
            }
        }
        buf ^= 1;
    }

    // epilogue: out[b][co][hw], px tile within one image
    const int b = px0 / HW;
    const int hwb = px0 - b * HW;
    #pragma unroll
    for (int mt = 0; mt < 2; mt++) {
        #pragma unroll
        for (int nt = 0; nt < 4; nt++) {
            int m0 = warpM + mt * 16 + g;
            int n0 = warpN + nt * 8 + 2 * t;
            float* o0 = out + ((size_t)(b * 64 + n0)) * HW + hwb;
            float* o1 = out + ((size_t)(b * 64 + n0 + 1)) * HW + hwb;
            o0[m0]     = fmaxf(acc[mt][nt][0], 0.f);
            o1[m0]     = fmaxf(acc[mt][nt][1], 0.f);
            o0[m0 + 8] = fmaxf(acc[mt][nt][2], 0.f);
            o1[m0 + 8] = fmaxf(acc[mt][nt][3], 0.f);
        }
    }
}

// ---------------------------------------------------------------------------
extern "C" void kernel_launch(void* const* d_in, const int* in_sizes, int n_in,
                              void* d_out, int out_size) {
    const float* x  = (const float*)d_in[0];
    const float* Wq = (const float*)d_in[1];
    const float* Wk = (const float*)d_in[2];
    const float* Wv = (const float*)d_in[3];
    const float* Wu = (const float*)d_in[4];
    float* out = (float*)d_out;

    prep_w<<<(3 * 9 * 64 * 512 + 255) / 256, 256>>>(Wq, Wk, Wv, Wu);
    im2col<<<dim3(NPX / 256, KTOT), 256>>>(x);
    conv_mma<<<dim3(NPX / BM, 512 / BN, 3), 128>>>();
    attn_kernel<<<NPX / 4, 256>>>();
    wu_mma<<<NPX / 64, 128>>>(out);
}

// round 4
// speedup vs baseline: 5.2216x; 1.0869x over previous
#include <cuda_runtime.h>
#include <cuda_bf16.h>
#include <cstdint>

#define B_    8
#define CIN   64
#define HDIM  56
#define WDIM  56
#define HW    3136
#define NPX   25088
#define KTOT  576

__device__ float g_qkv[3ull * NPX * 512];
__device__ float g_att[(unsigned long long)NPX * 512];   // [px][qc*8+n] tf32
__device__ float g_col[(unsigned long long)KTOT * NPX];  // [k][px] tf32
__device__ float g_Wt[3 * 9 * 64 * 512];                 // [proj][tap][ic][oc] tf32
__device__ float g_Wut[512 * 64];                        // [k][co] tf32

__device__ __forceinline__ float to_tf32(float x) {
    unsigned u;
    asm("cvt.rna.tf32.f32 %0, %1;" : "=r"(u) : "f"(x));
    return __uint_as_float(u);
}

__device__ __forceinline__ void cp_async16(void* smem, const void* gmem) {
    unsigned saddr = (unsigned)__cvta_generic_to_shared(smem);
    asm volatile("cp.async.cg.shared.global [%0], [%1], 16;" :: "r"(saddr), "l"(gmem));
}
__device__ __forceinline__ void cp_commit() { asm volatile("cp.async.commit_group;"); }
__device__ __forceinline__ void cp_wait0() { asm volatile("cp.async.wait_group 0;"); }

#define MMA_TF32(acc, a, b)                                                     \
    asm volatile(                                                               \
        "mma.sync.aligned.m16n8k8.row.col.f32.tf32.tf32.f32 "                   \
        "{%0,%1,%2,%3}, {%4,%5,%6,%7}, {%8,%9}, {%0,%1,%2,%3};"                 \
        : "+f"((acc)[0]), "+f"((acc)[1]), "+f"((acc)[2]), "+f"((acc)[3])        \
        : "r"(__float_as_uint((a)[0])), "r"(__float_as_uint((a)[1])),           \
          "r"(__float_as_uint((a)[2])), "r"(__float_as_uint((a)[3])),           \
          "r"(__float_as_uint((b)[0])), "r"(__float_as_uint((b)[1])))

// ---------------------------------------------------------------------------
__global__ void prep_w(const float* __restrict__ Wq, const float* __restrict__ Wk,
                       const float* __restrict__ Wv, const float* __restrict__ Wu) {
    int idx = blockIdx.x * blockDim.x + threadIdx.x;
    const int tot = 3 * 9 * 64 * 512;
    if (idx < tot) {
        int oc = idx & 511;
        int t = idx >> 9;
        int ic = t & 63; t >>= 6;
        int tap = t % 9;
        int proj = t / 9;
        const float* src = (proj == 0) ? Wq : ((proj == 1) ? Wk : Wv);
        g_Wt[idx] = to_tf32(src[(oc * 64 + ic) * 9 + tap]);
    }
    if (idx < 512 * 64) {
        int co = idx & 63;
        int k = idx >> 6;
        g_Wut[idx] = to_tf32(Wu[co * 512 + k]);
    }
}

// ---------------------------------------------------------------------------
__global__ __launch_bounds__(256) void im2col(const float* __restrict__ x) {
    const int px = blockIdx.x * 256 + threadIdx.x;
    const int k = blockIdx.y;
    const int tap = k >> 6;
    const int ic = k & 63;
    const int dr = tap / 3 - 1;
    const int dc = tap % 3 - 1;
    const int b = px / HW;
    const int rem = px - b * HW;
    const int h = rem / WDIM;
    const int w = rem - h * WDIM;
    const int hh = h + dr, ww = w + dc;
    float v = 0.f;
    if (hh >= 0 && hh < HDIM && ww >= 0 && ww < WDIM)
        v = x[((size_t)(b * CIN + ic)) * HW + hh * WDIM + ww];
    g_col[(size_t)k * NPX + px] = to_tf32(v);
}

// ---------------------------------------------------------------------------
// qkv conv GEMM, tf32 mma, 2-stage cp.async pipeline. BM=128 BN=128 BK=16.
// ---------------------------------------------------------------------------
#define BM 128
#define BN 128
#define BKc 16
#define SSTR 136

__global__ __launch_bounds__(128, 2) void conv_mma() {
    __shared__ float As[2][BKc][SSTR];   // [k][m(px)]
    __shared__ float Bs[2][BKc][SSTR];   // [k][n(oc)]

    const int tid = threadIdx.x;
    const int warp = tid >> 5;
    const int lane = tid & 31;
    const int g = lane >> 2;
    const int t = lane & 3;

    const int px0 = blockIdx.x * BM;
    const int oc0 = blockIdx.y * BN;
    const int proj = blockIdx.z;
    const int warpM = (warp & 1) * 64;
    const int warpN = (warp >> 1) * 64;

    const float* wsrc = g_Wt + (size_t)proj * (KTOT * 512);

    float acc[4][8][4];
    #pragma unroll
    for (int mt = 0; mt < 4; mt++)
        #pragma unroll
        for (int nt = 0; nt < 8; nt++)
            #pragma unroll
            for (int r = 0; r < 4; r++) acc[mt][nt][r] = 0.f;

    #pragma unroll
    for (int i = 0; i < 4; i++) {
        int idx = i * 128 + tid;
        int row = idx >> 5;
        int col = (idx & 31) << 2;
        cp_async16(&As[0][row][col], g_col + (size_t)row * NPX + px0 + col);
        cp_async16(&Bs[0][row][col], wsrc + (size_t)row * 512 + oc0 + col);
    }
    cp_commit();

    int buf = 0;
    for (int k0 = 0; k0 < KTOT; k0 += BKc) {
        cp_wait0();
        __syncthreads();

        const int kn = k0 + BKc;
        if (kn < KTOT) {
            const int nb = buf ^ 1;
            #pragma unroll
            for (int i = 0; i < 4; i++) {
                int idx = i * 128 + tid;
                int row = idx >> 5;
                int col = (idx & 31) << 2;
                cp_async16(&As[nb][row][col], g_col + (size_t)(kn + row) * NPX + px0 + col);
                cp_async16(&Bs[nb][row][col], wsrc + (size_t)(kn + row) * 512 + oc0 + col);
            }
            cp_commit();
        }

        #pragma unroll
        for (int ks = 0; ks < 2; ks++) {
            const int kb = ks * 8;
            float af[4][4];
            #pragma unroll
            for (int mt = 0; mt < 4; mt++) {
                int m = warpM + mt * 16 + g;
                af[mt][0] = As[buf][kb + t][m];
                af[mt][1] = As[buf][kb + t][m + 8];
                af[mt][2] = As[buf][kb + t + 4][m];
                af[mt][3] = As[buf][kb + t + 4][m + 8];
            }
            float bf[8][2];
            #pragma unroll
            for (int nt = 0; nt < 8; nt++) {
                int n = warpN + nt * 8 + g;
                bf[nt][0] = Bs[buf][kb + t][n];
                bf[nt][1] = Bs[buf][kb + t + 4][n];
            }
            #pragma unroll
            for (int mt = 0; mt < 4; mt++)
                #pragma unroll
                for (int nt = 0; nt < 8; nt++)
                    MMA_TF32(acc[mt][nt], af[mt], bf[nt]);
        }
        buf ^= 1;
    }

    float* outp = g_qkv + (size_t)proj * NPX * 512;
    #pragma unroll
    for (int mt = 0; mt < 4; mt++) {
        #pragma unroll
        for (int nt = 0; nt < 8; nt++) {
            int r0 = px0 + warpM + mt * 16 + g;
            int c0 = oc0 + warpN + nt * 8 + 2 * t;
            *(float2*)(outp + (size_t)r0 * 512 + c0) = make_float2(acc[mt][nt][0], acc[mt][nt][1]);
            *(float2*)(outp + (size_t)(r0 + 8) * 512 + c0) = make_float2(acc[mt][nt][2], acc[mt][nt][3]);
        }
    }
}

// ---------------------------------------------------------------------------
// Tensor-core per-pixel channel attention. 1 warp = 1 pixel; 8 px/block.
// scores: M=64(qc) x N=64(kc) x K=8(heads) tf32 mma, fragments straight from
// gmem (each element exactly once, sector-aligned). Softmax per row within a
// thread-quad (2 shfl_xor). attended: M=64 x N=8(heads) x K=64(kc); P moved
// from C-frag to A-frag layout by quad shuffles. Row-normalize at epilogue.
// ---------------------------------------------------------------------------
__global__ __launch_bounds__(256) void attn_mma() {
    const int warp = threadIdx.x >> 5;
    const int lane = threadIdx.x & 31;
    const int g = lane >> 2;
    const int t = lane & 3;
    const int p = blockIdx.x * 8 + warp;
    const size_t base = (size_t)p * 512;
    const float* qp = g_qkv + base;
    const float* kp = g_qkv + (size_t)NPX * 512 + base;
    const float* vp = g_qkv + 2ull * NPX * 512 + base;
    const float scale = 0.04419417382415922f;   // 1/sqrt(512)

    // k fragments (B for scores): b[n=kc][k=head]; v fragments (B for attended):
    // b[n=head][k=kc]. Both reused across all m-tiles.
    float kb[8][2], vb[8][2];
    #pragma unroll
    for (int nt = 0; nt < 8; nt++) {
        kb[nt][0] = to_tf32(kp[t * 64 + nt * 8 + g]);
        kb[nt][1] = to_tf32(kp[(t + 4) * 64 + nt * 8 + g]);
        vb[nt][0] = to_tf32(vp[g * 64 + nt * 8 + t]);
        vb[nt][1] = to_tf32(vp[g * 64 + nt * 8 + t + 4]);
    }

    const int srcA = (lane & ~3) | (t >> 1);
    const int srcB = srcA + 2;
    const bool odd = (t & 1);

    #pragma unroll
    for (int mt = 0; mt < 4; mt++) {
        // A fragment (q): a[m=qc][k=head]
        float aq[4];
        aq[0] = to_tf32(qp[t * 64 + mt * 16 + g] * scale);
        aq[1] = to_tf32(qp[t * 64 + mt * 16 + 8 + g] * scale);
        aq[2] = to_tf32(qp[(t + 4) * 64 + mt * 16 + g] * scale);
        aq[3] = to_tf32(qp[(t + 4) * 64 + mt * 16 + 8 + g] * scale);

        float S[8][4];
        #pragma unroll
        for (int nt = 0; nt < 8; nt++) {
            S[nt][0] = 0.f; S[nt][1] = 0.f; S[nt][2] = 0.f; S[nt][3] = 0.f;
            MMA_TF32(S[nt], aq, kb[nt]);
        }

        // row max (rows: g -> regs 0/1, g+8 -> regs 2/3)
        float m0 = -1e30f, m1 = -1e30f;
        #pragma unroll
        for (int nt = 0; nt < 8; nt++) {
            m0 = fmaxf(m0, fmaxf(S[nt][0], S[nt][1]));
            m1 = fmaxf(m1, fmaxf(S[nt][2], S[nt][3]));
        }
        m0 = fmaxf(m0, __shfl_xor_sync(0xffffffffu, m0, 1));
        m0 = fmaxf(m0, __shfl_xor_sync(0xffffffffu, m0, 2));
        m1 = fmaxf(m1, __shfl_xor_sync(0xffffffffu, m1, 1));
        m1 = fmaxf(m1, __shfl_xor_sync(0xffffffffu, m1, 2));

        // exp (tf32-rounded for the next MMA) + row sums
        float s0 = 0.f, s1 = 0.f;
        #pragma unroll
        for (int nt = 0; nt < 8; nt++) {
            float e0 = to_tf32(__expf(S[nt][0] - m0));
            float e1 = to_tf32(__expf(S[nt][1] - m0));
            float e2 = to_tf32(__expf(S[nt][2] - m1));
            float e3 = to_tf32(__expf(S[nt][3] - m1));
            S[nt][0] = e0; S[nt][1] = e1; S[nt][2] = e2; S[nt][3] = e3;
            s0 += e0 + e1;
            s1 += e2 + e3;
        }
        s0 += __shfl_xor_sync(0xffffffffu, s0, 1);
        s0 += __shfl_xor_sync(0xffffffffu, s0, 2);
        s1 += __shfl_xor_sync(0xffffffffu, s1, 1);
        s1 += __shfl_xor_sync(0xffffffffu, s1, 2);
        const float inv0 = 1.0f / s0;
        const float inv1 = 1.0f / s1;

        // attended: O[qc][head] = sum_kc P[qc][kc] * V[kc][head]
        float o[4] = {0.f, 0.f, 0.f, 0.f};
        #pragma unroll
        for (int kt = 0; kt < 8; kt++) {
            float eA  = __shfl_sync(0xffffffffu, S[kt][0], srcA);
            float oA  = __shfl_sync(0xffffffffu, S[kt][1], srcA);
            float fA  = __shfl_sync(0xffffffffu, S[kt][2], srcA);
            float hA  = __shfl_sync(0xffffffffu, S[kt][3], srcA);
            float eB  = __shfl_sync(0xffffffffu, S[kt][0], srcB);
            float oB  = __shfl_sync(0xffffffffu, S[kt][1], srcB);
            float fB  = __shfl_sync(0xffffffffu, S[kt][2], srcB);
            float hB  = __shfl_sync(0xffffffffu, S[kt][3], srcB);
            float a2[4];
            a2[0] = odd ? oA : eA;   // P[g   ][kt*8+t  ]
            a2[1] = odd ? hA : fA;   // P[g+8 ][kt*8+t  ]
            a2[2] = odd ? oB : eB;   // P[g   ][kt*8+t+4]
            a2[3] = odd ? hB : fB;   // P[g+8 ][kt*8+t+4]
            MMA_TF32(o, a2, vb[kt]);
        }
        o[0] *= inv0; o[1] *= inv0;
        o[2] *= inv1; o[3] *= inv1;

        // g_att[px][qc*8 + head]; O cols (heads) 2t, 2t+1 -> float2
        float* ap = g_att + base + (size_t)(mt * 16 + g) * 8 + 2 * t;
        *(float2*)ap = make_float2(o[0], o[1]);
        *(float2*)(ap + 64) = make_float2(o[2], o[3]);   // row g+8
    }
}

// ---------------------------------------------------------------------------
// 1x1 conv (Wu) + ReLU as tf32 MMA GEMM. M=px(64 tile), N=co(64), K=512.
// ---------------------------------------------------------------------------
#define WUS 72

__global__ __launch_bounds__(128) void wu_mma(float* __restrict__ out) {
    __shared__ float Ats[2][32][WUS];   // [k][px]
    __shared__ float Ws[2][32][WUS];    // [k][co]

    const int tid = threadIdx.x;
    const int warp = tid >> 5;
    const int lane = tid & 31;
    const int g = lane >> 2;
    const int t = lane & 3;

    const int px0 = blockIdx.x * 64;
    const int warpM = (warp & 1) * 32;
    const int warpN = (warp >> 1) * 32;

    float acc[2][4][4];
    #pragma unroll
    for (int mt = 0; mt < 2; mt++)
        #pragma unroll
        for (int nt = 0; nt < 4; nt++)
            #pragma unroll
            for (int r = 0; r < 4; r++) acc[mt][nt][r] = 0.f;

    {
        if (tid < 64) {
            const float* src = g_att + (size_t)(px0 + tid) * 512;
            #pragma unroll
            for (int j = 0; j < 8; j++) {
                float4 v = *(const float4*)(src + j * 4);
                Ats[0][j * 4 + 0][tid] = v.x;
                Ats[0][j * 4 + 1][tid] = v.y;
                Ats[0][j * 4 + 2][tid] = v.z;
                Ats[0][j * 4 + 3][tid] = v.w;
            }
        } else {
            int t2 = tid - 64;
            #pragma unroll
            for (int i = 0; i < 8; i++) {
                int idx = t2 + i * 64;
                int row = idx >> 4;
                int col = (idx & 15) * 4;
                cp_async16(&Ws[0][row][col], g_Wut + row * 64 + col);
            }
        }
        cp_commit();
    }

    int buf = 0;
    for (int k0 = 0; k0 < 512; k0 += 32) {
        cp_wait0();
        __syncthreads();

        const int kn = k0 + 32;
        if (kn < 512) {
            const int nb = buf ^ 1;
            if (tid < 64) {
                const float* src = g_att + (size_t)(px0 + tid) * 512 + kn;
                #pragma unroll
                for (int j = 0; j < 8; j++) {
                    float4 v = *(const float4*)(src + j * 4);
                    Ats[nb][j * 4 + 0][tid] = v.x;
                    Ats[nb][j * 4 + 1][tid] = v.y;
                    Ats[nb][j * 4 + 2][tid] = v.z;
                    Ats[nb][j * 4 + 3][tid] = v.w;
                }
            } else {
                int t2 = tid - 64;
                #pragma unroll
                for (int i = 0; i < 8; i++) {
                    int idx = t2 + i * 64;
                    int row = idx >> 4;
                    int col = (idx & 15) * 4;
                    cp_async16(&Ws[nb][row][col], g_Wut + (kn + row) * 64 + col);
                }
            }
            cp_commit();
        }

        #pragma unroll
        for (int ks = 0; ks < 4; ks++) {
            const int kb = ks * 8;
            float af[2][4];
            #pragma unroll
            for (int mt = 0; mt < 2; mt++) {
                int mm = warpM + mt * 16 + g;
                af[mt][0] = Ats[buf][kb + t][mm];
                af[mt][1] = Ats[buf][kb + t][mm + 8];
                af[mt][2] = Ats[buf][kb + t + 4][mm];
                af[mt][3] = Ats[buf][kb + t + 4][mm + 8];
            }
            float bf[4][2];
            #pragma unroll
            for (int nt = 0; nt < 4; nt++) {
                int n = warpN + nt * 8 + g;
                bf[nt][0] = Ws[buf][kb + t][n];
                bf[nt][1] = Ws[buf][kb + t + 4][n];
            }
            #pragma unroll
            for (int mt = 0; mt < 2; mt++)
                #pragma unroll
                for (int nt = 0; nt < 4; nt++)
                    MMA_TF32(acc[mt][nt], af[mt], bf[nt]);
        }
        buf ^= 1;
    }

    const int b = px0 / HW;
    const int hwb = px0 - b * HW;
    #pragma unroll
    for (int mt = 0; mt < 2; mt++) {
        #pragma unroll
        for (int nt = 0; nt < 4; nt++) {
            int m0 = warpM + mt * 16 + g;
            int n0 = warpN + nt * 8 + 2 * t;
            float* o0 = out + ((size_t)(b * 64 + n0)) * HW + hwb;
            float* o1 = out + ((size_t)(b * 64 + n0 + 1)) * HW + hwb;
            o0[m0]     = fmaxf(acc[mt][nt][0], 0.f);
            o1[m0]     = fmaxf(acc[mt][nt][1], 0.f);
            o0[m0 + 8] = fmaxf(acc[mt][nt][2], 0.f);
            o1[m0 + 8] = fmaxf(acc[mt][nt][3], 0.f);
        }
    }
}

// ---------------------------------------------------------------------------
extern "C" void kernel_launch(void* const* d_in, const int* in_sizes, int n_in,
                              void* d_out, int out_size) {
    const float* x  = (const float*)d_in[0];
    const float* Wq = (const float*)d_in[1];
    const float* Wk = (const float*)d_in[2];
    const float* Wv = (const float*)d_in[3];
    const float* Wu = (const float*)d_in[4];
    float* out = (float*)d_out;

    prep_w<<<(3 * 9 * 64 * 512 + 255) / 256, 256>>>(Wq, Wk, Wv, Wu);
    im2col<<<dim3(NPX / 256, KTOT), 256>>>(x);
    conv_mma<<<dim3(NPX / BM, 512 / BN, 3), 128>>>();
    attn_mma<<<NPX / 8, 256>>>();
    wu_mma<<<NPX / 64, 128>>>(out);
}

// round 6
// speedup vs baseline: 7.0557x; 1.3513x over previous
#include <cuda_runtime.h>
#include <cuda_fp16.h>
#include <cstdint>

#define B_    8
#define CIN   64
#define HDIM  56
#define WDIM  56
#define HW    3136
#define NPX   25088
#define KTOT  576

__device__ float  g_qkv[3ull * NPX * 512];                 // [proj][px][oc] f32
__device__ __half g_atth[(unsigned long long)NPX * 512];   // [px][qc*8+n] f16
__device__ __half g_colh[(unsigned long long)NPX * KTOT];  // [px][k] f16
__device__ __half g_Wth[3ull * 512 * KTOT];                // [proj][oc][k] f16
__device__ __half g_Wuh[64 * 512];                         // [co][k] f16

__device__ __forceinline__ float to_tf32(float x) {
    unsigned u;
    asm("cvt.rna.tf32.f32 %0, %1;" : "=r"(u) : "f"(x));
    return __uint_as_float(u);
}
__device__ __forceinline__ void cp_async16(void* smem, const void* gmem) {
    unsigned saddr = (unsigned)__cvta_generic_to_shared(smem);
    asm volatile("cp.async.cg.shared.global [%0], [%1], 16;" :: "r"(saddr), "l"(gmem));
}
__device__ __forceinline__ void cp_commit() { asm volatile("cp.async.commit_group;"); }
__device__ __forceinline__ void cp_wait0() { asm volatile("cp.async.wait_group 0;"); }
__device__ __forceinline__ void cp_wait1() { asm volatile("cp.async.wait_group 1;"); }

// f16 mma m16n8k16, fp32 accumulate
#define MMA_F16(acc, a, b)                                                      \
    asm volatile(                                                               \
        "mma.sync.aligned.m16n8k16.row.col.f32.f16.f16.f32 "                    \
        "{%0,%1,%2,%3}, {%4,%5,%6,%7}, {%8,%9}, {%0,%1,%2,%3};"                 \
        : "+f"((acc)[0]), "+f"((acc)[1]), "+f"((acc)[2]), "+f"((acc)[3])        \
        : "r"((a)[0]), "r"((a)[1]), "r"((a)[2]), "r"((a)[3]),                   \
          "r"((b)[0]), "r"((b)[1]))

// tf32 mma m16n8k8 (attention internals)
#define MMA_TF32(acc, a, b)                                                     \
    asm volatile(                                                               \
        "mma.sync.aligned.m16n8k8.row.col.f32.tf32.tf32.f32 "                   \
        "{%0,%1,%2,%3}, {%4,%5,%6,%7}, {%8,%9}, {%0,%1,%2,%3};"                 \
        : "+f"((acc)[0]), "+f"((acc)[1]), "+f"((acc)[2]), "+f"((acc)[3])        \
        : "r"(__float_as_uint((a)[0])), "r"(__float_as_uint((a)[1])),           \
          "r"(__float_as_uint((a)[2])), "r"(__float_as_uint((a)[3])),           \
          "r"(__float_as_uint((b)[0])), "r"(__float_as_uint((b)[1])))

// ---------------------------------------------------------------------------
// Weight prep (f16): g_Wth[proj][oc][tap*64+ic]; g_Wuh[co][k] (native layout).
// ---------------------------------------------------------------------------
__global__ void prep_wh(const float* __restrict__ Wq, const float* __restrict__ Wk,
                        const float* __restrict__ Wv, const float* __restrict__ Wu) {
    int idx = blockIdx.x * blockDim.x + threadIdx.x;
    const int tot = 3 * 512 * KTOT;
    if (idx < tot) {
        int k = idx % KTOT;
        int oc = (idx / KTOT) & 511;
        int proj = idx / (KTOT * 512);
        int tap = k >> 6;
        int ic = k & 63;
        const float* src = (proj == 0) ? Wq : ((proj == 1) ? Wk : Wv);
        g_Wth[idx] = __float2half_rn(src[(oc * 64 + ic) * 9 + tap]);
    }
    if (idx < 64 * 512) {
        g_Wuh[idx] = __float2half_rn(Wu[idx]);   // [co][k], k contiguous, as-is
    }
}

// ---------------------------------------------------------------------------
// im2col f16, K-major: g_colh[px][576]. One block per (b, h) row of the image.
// ---------------------------------------------------------------------------
__global__ __launch_bounds__(256) void im2colh(const float* __restrict__ x) {
    __shared__ float xs[64][3][61];   // [ic][r][1+w]
    const int b = blockIdx.x / HDIM;
    const int h = blockIdx.x % HDIM;
    const int tid = threadIdx.x;

    for (int i = tid; i < 64 * 3 * 61; i += 256)
        ((float*)xs)[i] = 0.f;
    __syncthreads();

    #pragma unroll
    for (int r = 0; r < 3; r++) {
        const int hh = h - 1 + r;
        if (hh >= 0 && hh < HDIM) {
            for (int i = tid; i < 64 * 56; i += 256) {
                int ic = i / 56;
                int w = i - ic * 56;
                xs[ic][r][1 + w] = x[((size_t)(b * CIN + ic)) * HW + hh * WDIM + w];
            }
        }
    }
    __syncthreads();

    __half* outb = g_colh + ((size_t)(b * HW + h * WDIM)) * KTOT;
    for (int i = tid; i < 56 * KTOT; i += 256) {
        int w = i / KTOT;
        int k = i - w * KTOT;
        int tap = k >> 6;
        int ic = k & 63;
        int dr = tap / 3;
        int dc = tap % 3;
        outb[(size_t)w * KTOT + k] = __float2half_rn(xs[ic][dr][w + dc]);
    }
}

// ---------------------------------------------------------------------------
// qkv conv GEMM, f16 m16n8k16, true 2-stage cp.async pipeline.
// BM=128(px) BN=128(oc) BK=32; 128 threads, 4 warps (2x2), warp tile 64x64.
// Smem row-major [m][k] / [n][k], row stride 40 halves -> conflict-free LDS.
// grid = (196, 4, 3)
// ---------------------------------------------------------------------------
#define NITER 18

__global__ __launch_bounds__(128) void conv_f16() {
    __shared__ __half As[2][128][40];   // [px][k]
    __shared__ __half Bs[2][128][40];   // [oc][k]

    const int tid = threadIdx.x;
    const int warp = tid >> 5;
    const int lane = tid & 31;
    const int g = lane >> 2;
    const int t = lane & 3;

    const int px0 = blockIdx.x * 128;
    const int oc0 = blockIdx.y * 128;
    const int proj = blockIdx.z;
    const int warpM = (warp & 1) * 64;
    const int warpN = (warp >> 1) * 64;

    const __half* asrc = g_colh + (size_t)px0 * KTOT;
    const __half* bsrc = g_Wth + ((size_t)proj * 512 + oc0) * KTOT;

    float acc[4][8][4];
    #pragma unroll
    for (int mt = 0; mt < 4; mt++)
        #pragma unroll
        for (int nt = 0; nt < 8; nt++)
            #pragma unroll
            for (int r = 0; r < 4; r++) acc[mt][nt][r] = 0.f;

    auto fill = [&](int buf, int kk) {
        const int kof = kk * 32;
        #pragma unroll
        for (int i = 0; i < 4; i++) {
            int id = i * 128 + tid;      // 0..511
            int row = id >> 2;           // 0..127
            int c = id & 3;              // 16B chunk (8 halves)
            cp_async16(&As[buf][row][c * 8], asrc + (size_t)row * KTOT + kof + c * 8);
            cp_async16(&Bs[buf][row][c * 8], bsrc + (size_t)row * KTOT + kof + c * 8);
        }
        cp_commit();
    };

    fill(0, 0);
    fill(1, 1);

    for (int kk = 0; kk < NITER; kk++) {
        const int buf = kk & 1;
        if (kk == NITER - 1) cp_wait0(); else cp_wait1();
        __syncthreads();

        #pragma unroll
        for (int ks = 0; ks < 2; ks++) {
            const int kb = ks * 16;
            uint32_t af[4][4];
            #pragma unroll
            for (int mt = 0; mt < 4; mt++) {
                int m = warpM + mt * 16 + g;
                af[mt][0] = *(const uint32_t*)&As[buf][m][kb + 2 * t];
                af[mt][1] = *(const uint32_t*)&As[buf][m + 8][kb + 2 * t];
                af[mt][2] = *(const uint32_t*)&As[buf][m][kb + 2 * t + 8];
                af[mt][3] = *(const uint32_t*)&As[buf][m + 8][kb + 2 * t + 8];
            }
            uint32_t bf[8][2];
            #pragma unroll
            for (int nt = 0; nt < 8; nt++) {
                int n = warpN + nt * 8 + g;
                bf[nt][0] = *(const uint32_t*)&Bs[buf][n][kb + 2 * t];
                bf[nt][1] = *(const uint32_t*)&Bs[buf][n][kb + 2 * t + 8];
            }
            #pragma unroll
            for (int mt = 0; mt < 4; mt++)
                #pragma unroll
                for (int nt = 0; nt < 8; nt++)
                    MMA_F16(acc[mt][nt], af[mt], bf[nt]);
        }

        if (kk + 2 < NITER) {
            __syncthreads();            // all warps done reading buf
            fill(buf, kk + 2);
        }
    }

    float* outp = g_qkv + (size_t)proj * NPX * 512;
    #pragma unroll
    for (int mt = 0; mt < 4; mt++) {
        #pragma unroll
        for (int nt = 0; nt < 8; nt++) {
            int r0 = px0 + warpM + mt * 16 + g;
            int c0 = oc0 + warpN + nt * 8 + 2 * t;
            *(float2*)(outp + (size_t)r0 * 512 + c0) = make_float2(acc[mt][nt][0], acc[mt][nt][1]);
            *(float2*)(outp + (size_t)(r0 + 8) * 512 + c0) = make_float2(acc[mt][nt][2], acc[mt][nt][3]);
        }
    }
}

// ---------------------------------------------------------------------------
// Tensor-core per-pixel channel attention (round-4 proven); f16 epilogue.
// ---------------------------------------------------------------------------
__global__ __launch_bounds__(256) void attn_mma() {
    const int warp = threadIdx.x >> 5;
    const int lane = threadIdx.x & 31;
    const int g = lane >> 2;
    const int t = lane & 3;
    const int p = blockIdx.x * 8 + warp;
    const size_t base = (size_t)p * 512;
    const float* qp = g_qkv + base;
    const float* kp = g_qkv + (size_t)NPX * 512 + base;
    const float* vp = g_qkv + 2ull * NPX * 512 + base;
    const float scale = 0.04419417382415922f;   // 1/sqrt(512)

    float kb[8][2], vb[8][2];
    #pragma unroll
    for (int nt = 0; nt < 8; nt++) {
        kb[nt][0] = to_tf32(kp[t * 64 + nt * 8 + g]);
        kb[nt][1] = to_tf32(kp[(t + 4) * 64 + nt * 8 + g]);
        vb[nt][0] = to_tf32(vp[g * 64 + nt * 8 + t]);
        vb[nt][1] = to_tf32(vp[g * 64 + nt * 8 + t + 4]);
    }

    const int srcA = (lane & ~3) | (t >> 1);
    const int srcB = srcA + 2;
    const bool odd = (t & 1);

    #pragma unroll
    for (int mt = 0; mt < 4; mt++) {
        float aq[4];
        aq[0] = to_tf32(qp[t * 64 + mt * 16 + g] * scale);
        aq[1] = to_tf32(qp[t * 64 + mt * 16 + 8 + g] * scale);
        aq[2] = to_tf32(qp[(t + 4) * 64 + mt * 16 + g] * scale);
        aq[3] = to_tf32(qp[(t + 4) * 64 + mt * 16 + 8 + g] * scale);

        float S[8][4];
        #pragma unroll
        for (int nt = 0; nt < 8; nt++) {
            S[nt][0] = 0.f; S[nt][1] = 0.f; S[nt][2] = 0.f; S[nt][3] = 0.f;
            MMA_TF32(S[nt], aq, kb[nt]);
        }

        float m0 = -1e30f, m1 = -1e30f;
        #pragma unroll
        for (int nt = 0; nt < 8; nt++) {
            m0 = fmaxf(m0, fmaxf(S[nt][0], S[nt][1]));
            m1 = fmaxf(m1, fmaxf(S[nt][2], S[nt][3]));
        }
        m0 = fmaxf(m0, __shfl_xor_sync(0xffffffffu, m0, 1));
        m0 = fmaxf(m0, __shfl_xor_sync(0xffffffffu, m0, 2));
        m1 = fmaxf(m1, __shfl_xor_sync(0xffffffffu, m1, 1));
        m1 = fmaxf(m1, __shfl_xor_sync(0xffffffffu, m1, 2));

        float s0 = 0.f, s1 = 0.f;
        #pragma unroll
        for (int nt = 0; nt < 8; nt++) {
            float e0 = to_tf32(__expf(S[nt][0] - m0));
            float e1 = to_tf32(__expf(S[nt][1] - m0));
            float e2 = to_tf32(__expf(S[nt][2] - m1));
            float e3 = to_tf32(__expf(S[nt][3] - m1));
            S[nt][0] = e0; S[nt][1] = e1; S[nt][2] = e2; S[nt][3] = e3;
            s0 += e0 + e1;
            s1 += e2 + e3;
        }
        s0 += __shfl_xor_sync(0xffffffffu, s0, 1);
        s0 += __shfl_xor_sync(0xffffffffu, s0, 2);
        s1 += __shfl_xor_sync(0xffffffffu, s1, 1);
        s1 += __shfl_xor_sync(0xffffffffu, s1, 2);
        const float inv0 = 1.0f / s0;
        const float inv1 = 1.0f / s1;

        float o[4] = {0.f, 0.f, 0.f, 0.f};
        #pragma unroll
        for (int kt = 0; kt < 8; kt++) {
            float eA = __shfl_sync(0xffffffffu, S[kt][0], srcA);
            float oA = __shfl_sync(0xffffffffu, S[kt][1], srcA);
            float fA = __shfl_sync(0xffffffffu, S[kt][2], srcA);
            float hA = __shfl_sync(0xffffffffu, S[kt][3], srcA);
            float eB = __shfl_sync(0xffffffffu, S[kt][0], srcB);
            float oB = __shfl_sync(0xffffffffu, S[kt][1], srcB);
            float fB = __shfl_sync(0xffffffffu, S[kt][2], srcB);
            float hB = __shfl_sync(0xffffffffu, S[kt][3], srcB);
            float a2[4];
            a2[0] = odd ? oA : eA;
            a2[1] = odd ? hA : fA;
            a2[2] = odd ? oB : eB;
            a2[3] = odd ? hB : fB;
            MMA_TF32(o, a2, vb[kt]);
        }
        o[0] *= inv0; o[1] *= inv0;
        o[2] *= inv1; o[3] *= inv1;

        __half* ap = g_atth + base + (size_t)(mt * 16 + g) * 8 + 2 * t;
        *(__half2*)ap = __floats2half2_rn(o[0], o[1]);
        *(__half2*)(ap + 64) = __floats2half2_rn(o[2], o[3]);   // row g+8
    }
}

// ---------------------------------------------------------------------------
// 1x1 conv (Wu) + ReLU, f16 m16n8k16. BM=64(px) BN=64(co) BK=64; 256 threads,
// 8 warps (2M x 4N), warp tile 32x16. True 2-stage pipeline.
// ---------------------------------------------------------------------------
__global__ __launch_bounds__(256) void wu_f16(float* __restrict__ out) {
    __shared__ __half As[2][64][72];   // [px][k]
    __shared__ __half Bs[2][64][72];   // [co][k]

    const int tid = threadIdx.x;
    const int warp = tid >> 5;
    const int lane = tid & 31;
    const int g = lane >> 2;
    const int t = lane & 3;

    const int px0 = blockIdx.x * 64;
    const int wm = (warp & 1) * 32;
    const int wn = (warp >> 1) * 16;

    float acc[2][2][4];
    #pragma unroll
    for (int mt = 0; mt < 2; mt++)
        #pragma unroll
        for (int nt = 0; nt < 2; nt++)
            #pragma unroll
            for (int r = 0; r < 4; r++) acc[mt][nt][r] = 0.f;

    auto fill = [&](int stage, int k0) {
        #pragma unroll
        for (int i = 0; i < 2; i++) {
            int id = i * 256 + tid;      // 0..511
            int row = id >> 3;           // 0..63
            int c = id & 7;
            cp_async16(&As[stage][row][c * 8], g_atth + (size_t)(px0 + row) * 512 + k0 + c * 8);
            cp_async16(&Bs[stage][row][c * 8], g_Wuh + (size_t)row * 512 + k0 + c * 8);
        }
        cp_commit();
    };

    fill(0, 0);
    fill(1, 64);

    for (int it = 0; it < 8; it++) {
        const int buf = it & 1;
        if (it == 7) cp_wait0(); else cp_wait1();
        __syncthreads();

        #pragma unroll
        for (int ks = 0; ks < 4; ks++) {
            const int kb = ks * 16;
            uint32_t af[2][4];
            #pragma unroll
            for (int mt = 0; mt < 2; mt++) {
                int m = wm + mt * 16 + g;
                af[mt][0] = *(const uint32_t*)&As[buf][m][kb + 2 * t];
                af[mt][1] = *(const uint32_t*)&As[buf][m + 8][kb + 2 * t];
                af[mt][2] = *(const uint32_t*)&As[buf][m][kb + 2 * t + 8];
                af[mt][3] = *(const uint32_t*)&As[buf][m + 8][kb + 2 * t + 8];
            }
            uint32_t bf[2][2];
            #pragma unroll
            for (int nt = 0; nt < 2; nt++) {
                int n = wn + nt * 8 + g;
                bf[nt][0] = *(const uint32_t*)&Bs[buf][n][kb + 2 * t];
                bf[nt][1] = *(const uint32_t*)&Bs[buf][n][kb + 2 * t + 8];
            }
            #pragma unroll
            for (int mt = 0; mt < 2; mt++)
                #pragma unroll
                for (int nt = 0; nt < 2; nt++)
                    MMA_F16(acc[mt][nt], af[mt], bf[nt]);
        }

        if (it + 2 < 8) {
            __syncthreads();
            fill(buf, (it + 2) * 64);
        }
    }

    const int b = px0 / HW;
    const int hwb = px0 - b * HW;
    #pragma unroll
    for (int mt = 0; mt < 2; mt++) {
        #pragma unroll
        for (int nt = 0; nt < 2; nt++) {
            int m0 = wm + mt * 16 + g;
            int n0 = wn + nt * 8 + 2 * t;
            float* o0 = out + ((size_t)(b * 64 + n0)) * HW + hwb;
            float* o1 = out + ((size_t)(b * 64 + n0 + 1)) * HW + hwb;
            o0[m0]     = fmaxf(acc[mt][nt][0], 0.f);
            o1[m0]     = fmaxf(acc[mt][nt][1], 0.f);
            o0[m0 + 8] = fmaxf(acc[mt][nt][2], 0.f);
            o1[m0 + 8] = fmaxf(acc[mt][nt][3], 0.f);
        }
    }
}

// ---------------------------------------------------------------------------
extern "C" void kernel_launch(void* const* d_in, const int* in_sizes, int n_in,
                              void* d_out, int out_size) {
    const float* x  = (const float*)d_in[0];
    const float* Wq = (const float*)d_in[1];
    const float* Wk = (const float*)d_in[2];
    const float* Wv = (const float*)d_in[3];
    const float* Wu = (const float*)d_in[4];
    float* out = (float*)d_out;

    prep_wh<<<(3 * 512 * KTOT + 255) / 256, 256>>>(Wq, Wk, Wv, Wu);
    im2colh<<<B_ * HDIM, 256>>>(x);
    conv_f16<<<dim3(NPX / 128, 4, 3), 128>>>();
    attn_mma<<<NPX / 8, 256>>>();
    wu_f16<<<NPX / 64, 256>>>(out);
}

// round 7
// speedup vs baseline: 8.1132x; 1.1499x over previous
#include <cuda_runtime.h>
#include <cuda_fp16.h>
#include <cstdint>

#define B_    8
#define CIN   64
#define HDIM  56
#define WDIM  56
#define HW    3136
#define NPX   25088
#define KTOT  576

// qkv: proj 0 (q) and 1 (k) in "t-layout" [px][c*8+head] (pre-scaled q);
//      proj 2 (v) natural [px][head*64+c]. All f16.
__device__ __half g_qkvh[3ull * NPX * 512];
__device__ __half g_atth[(unsigned long long)NPX * 512];   // [px][qc*8+head]
__device__ __half g_colh[(unsigned long long)NPX * KTOT];  // [px][k]
__device__ __half g_Wth[3ull * 512 * KTOT];                // [proj][row][k] (rows permuted for q/k)
__device__ __half g_Wuh[64 * 512];                         // [co][k]

__device__ __forceinline__ void cp_async16(void* smem, const void* gmem) {
    unsigned saddr = (unsigned)__cvta_generic_to_shared(smem);
    asm volatile("cp.async.cg.shared.global [%0], [%1], 16;" :: "r"(saddr), "l"(gmem));
}
__device__ __forceinline__ void cp_commit() { asm volatile("cp.async.commit_group;"); }
__device__ __forceinline__ void cp_wait0() { asm volatile("cp.async.wait_group 0;"); }
__device__ __forceinline__ void cp_wait1() { asm volatile("cp.async.wait_group 1;"); }

// f16 mma m16n8k16, fp32 accumulate
#define MMA_F16(acc, a, b)                                                      \
    asm volatile(                                                               \
        "mma.sync.aligned.m16n8k16.row.col.f32.f16.f16.f32 "                    \
        "{%0,%1,%2,%3}, {%4,%5,%6,%7}, {%8,%9}, {%0,%1,%2,%3};"                 \
        : "+f"((acc)[0]), "+f"((acc)[1]), "+f"((acc)[2]), "+f"((acc)[3])        \
        : "r"((a)[0]), "r"((a)[1]), "r"((a)[2]), "r"((a)[3]),                   \
          "r"((b)[0]), "r"((b)[1]))

// f16 mma m16n8k8, fp32 accumulate
#define MMA_F16K8(acc, a, b)                                                    \
    asm volatile(                                                               \
        "mma.sync.aligned.m16n8k8.row.col.f32.f16.f16.f32 "                     \
        "{%0,%1,%2,%3}, {%4,%5}, {%6}, {%0,%1,%2,%3};"                          \
        : "+f"((acc)[0]), "+f"((acc)[1]), "+f"((acc)[2]), "+f"((acc)[3])        \
        : "r"((a)[0]), "r"((a)[1]), "r"(b))

__device__ __forceinline__ uint32_t packh2(float lo, float hi) {
    __half2 h = __floats2half2_rn(lo, hi);
    return *(uint32_t*)&h;
}

// ---------------------------------------------------------------------------
// Weight prep. For q/k, permute output rows: storage row r corresponds to
// original oc = (r&7)*64 + (r>>3)  (so conv output lands in t-layout).
// Fold 1/sqrt(512) into Wq.
// ---------------------------------------------------------------------------
__global__ void prep_wh(const float* __restrict__ Wq, const float* __restrict__ Wk,
                        const float* __restrict__ Wv, const float* __restrict__ Wu) {
    int idx = blockIdx.x * blockDim.x + threadIdx.x;
    const int tot = 3 * 512 * KTOT;
    if (idx < tot) {
        int k = idx % KTOT;
        int r = (idx / KTOT) & 511;
        int proj = idx / (KTOT * 512);
        int tap = k >> 6;
        int ic = k & 63;
        int oc = (proj < 2) ? ((r & 7) * 64 + (r >> 3)) : r;
        const float* src = (proj == 0) ? Wq : ((proj == 1) ? Wk : Wv);
        float w = src[(oc * 64 + ic) * 9 + tap];
        if (proj == 0) w *= 0.04419417382415922f;   // 1/sqrt(512)
        g_Wth[idx] = __float2half_rn(w);
    }
    if (idx < 64 * 512) {
        g_Wuh[idx] = __float2half_rn(Wu[idx]);   // [co][k] native
    }
}

// ---------------------------------------------------------------------------
// im2col f16, K-major: g_colh[px][576]. One block per (b, h) image row.
// ---------------------------------------------------------------------------
__global__ __launch_bounds__(256) void im2colh(const float* __restrict__ x) {
    __shared__ float xs[64][3][61];   // [ic][r][1+w]
    const int b = blockIdx.x / HDIM;
    const int h = blockIdx.x % HDIM;
    const int tid = threadIdx.x;

    for (int i = tid; i < 64 * 3 * 61; i += 256)
        ((float*)xs)[i] = 0.f;
    __syncthreads();

    #pragma unroll
    for (int r = 0; r < 3; r++) {
        const int hh = h - 1 + r;
        if (hh >= 0 && hh < HDIM) {
            for (int i = tid; i < 64 * 56; i += 256) {
                int ic = i / 56;
                int w = i - ic * 56;
                xs[ic][r][1 + w] = x[((size_t)(b * CIN + ic)) * HW + hh * WDIM + w];
            }
        }
    }
    __syncthreads();

    __half* outb = g_colh + ((size_t)(b * HW + h * WDIM)) * KTOT;
    for (int i = tid; i < 56 * KTOT; i += 256) {
        int w = i / KTOT;
        int k = i - w * KTOT;
        int tap = k >> 6;
        int ic = k & 63;
        int dr = tap / 3;
        int dc = tap % 3;
        outb[(size_t)w * KTOT + k] = __float2half_rn(xs[ic][dr][w + dc]);
    }
}

// ---------------------------------------------------------------------------
// qkv conv GEMM, f16 m16n8k16, 2-stage cp.async pipeline.
// BM=128 BN=128 BK=32; 128 threads, warp tile 64x64. f16 output.
// ---------------------------------------------------------------------------
#define NITER 18

__global__ __launch_bounds__(128) void conv_f16() {
    __shared__ __half As[2][128][40];   // [px][k]
    __shared__ __half Bs[2][128][40];   // [row][k]

    const int tid = threadIdx.x;
    const int warp = tid >> 5;
    const int lane = tid & 31;
    const int g = lane >> 2;
    const int t = lane & 3;

    const int px0 = blockIdx.x * 128;
    const int oc0 = blockIdx.y * 128;
    const int proj = blockIdx.z;
    const int warpM = (warp & 1) * 64;
    const int warpN = (warp >> 1) * 64;

    const __half* asrc = g_colh + (size_t)px0 * KTOT;
    const __half* bsrc = g_Wth + ((size_t)proj * 512 + oc0) * KTOT;

    float acc[4][8][4];
    #pragma unroll
    for (int mt = 0; mt < 4; mt++)
        #pragma unroll
        for (int nt = 0; nt < 8; nt++)
            #pragma unroll
            for (int r = 0; r < 4; r++) acc[mt][nt][r] = 0.f;

    auto fill = [&](int buf, int kk) {
        const int kof = kk * 32;
        #pragma unroll
        for (int i = 0; i < 4; i++) {
            int id = i * 128 + tid;
            int row = id >> 2;
            int c = id & 3;
            cp_async16(&As[buf][row][c * 8], asrc + (size_t)row * KTOT + kof + c * 8);
            cp_async16(&Bs[buf][row][c * 8], bsrc + (size_t)row * KTOT + kof + c * 8);
        }
        cp_commit();
    };

    fill(0, 0);
    fill(1, 1);

    for (int kk = 0; kk < NITER; kk++) {
        const int buf = kk & 1;
        if (kk == NITER - 1) cp_wait0(); else cp_wait1();
        __syncthreads();

        #pragma unroll
        for (int ks = 0; ks < 2; ks++) {
            const int kb = ks * 16;
            uint32_t af[4][4];
            #pragma unroll
            for (int mt = 0; mt < 4; mt++) {
                int m = warpM + mt * 16 + g;
                af[mt][0] = *(const uint32_t*)&As[buf][m][kb + 2 * t];
                af[mt][1] = *(const uint32_t*)&As[buf][m + 8][kb + 2 * t];
                af[mt][2] = *(const uint32_t*)&As[buf][m][kb + 2 * t + 8];
                af[mt][3] = *(const uint32_t*)&As[buf][m + 8][kb + 2 * t + 8];
            }
            uint32_t bf[8][2];
            #pragma unroll
            for (int nt = 0; nt < 8; nt++) {
                int n = warpN + nt * 8 + g;
                bf[nt][0] = *(const uint32_t*)&Bs[buf][n][kb + 2 * t];
                bf[nt][1] = *(const uint32_t*)&Bs[buf][n][kb + 2 * t + 8];
            }
            #pragma unroll
            for (int mt = 0; mt < 4; mt++)
                #pragma unroll
                for (int nt = 0; nt < 8; nt++)
                    MMA_F16(acc[mt][nt], af[mt], bf[nt]);
        }

        if (kk + 2 < NITER) {
            __syncthreads();
            fill(buf, kk + 2);
        }
    }

    __half* outp = g_qkvh + (size_t)proj * NPX * 512;
    #pragma unroll
    for (int mt = 0; mt < 4; mt++) {
        #pragma unroll
        for (int nt = 0; nt < 8; nt++) {
            int r0 = px0 + warpM + mt * 16 + g;
            int c0 = oc0 + warpN + nt * 8 + 2 * t;
            *(__half2*)(outp + (size_t)r0 * 512 + c0) =
                __floats2half2_rn(acc[mt][nt][0], acc[mt][nt][1]);
            *(__half2*)(outp + (size_t)(r0 + 8) * 512 + c0) =
                __floats2half2_rn(acc[mt][nt][2], acc[mt][nt][3]);
        }
    }
}

// ---------------------------------------------------------------------------
// f16 tensor-core attention, zero-shuffle P transpose.
// 1 warp = 1 pixel; 8 px/block. Q/K in t-layout -> contiguous half2 frags.
// S: m16n8k8 (K=heads); O: m16n8k16 with P packed straight from S C-frags.
// ---------------------------------------------------------------------------
__global__ __launch_bounds__(256) void attn_f16() {
    const int warp = threadIdx.x >> 5;
    const int lane = threadIdx.x & 31;
    const int g = lane >> 2;
    const int t = lane & 3;
    const int p = blockIdx.x * 8 + warp;
    const size_t base = (size_t)p * 512;
    const __half* qp = g_qkvh + base;                       // [qc*8+head], pre-scaled
    const __half* kp = g_qkvh + (size_t)NPX * 512 + base;   // [kc*8+head]
    const __half* vp = g_qkvh + 2ull * NPX * 512 + base;    // [head*64+kc]

    // K B-frags (scores): reg = (head=2t..2t+1, kc=nt*8+g) -> t-layout half2
    uint32_t kb[8];
    #pragma unroll
    for (int nt = 0; nt < 8; nt++)
        kb[nt] = *(const uint32_t*)&kp[(nt * 8 + g) * 8 + 2 * t];

    // V B-frags (O mma, k-tile q): reg0=(kc=16q+2t, head=g), reg1=(kc=16q+8+2t, g)
    uint32_t vb[4][2];
    #pragma unroll
    for (int q = 0; q < 4; q++) {
        vb[q][0] = *(const uint32_t*)&vp[g * 64 + 16 * q + 2 * t];
        vb[q][1] = *(const uint32_t*)&vp[g * 64 + 16 * q + 8 + 2 * t];
    }

    #pragma unroll
    for (int mt = 0; mt < 4; mt++) {
        // Q A-frag: (qc=mt*16+g / +8, head=2t..2t+1)
        uint32_t aq[2];
        aq[0] = *(const uint32_t*)&qp[(mt * 16 + g) * 8 + 2 * t];
        aq[1] = *(const uint32_t*)&qp[(mt * 16 + 8 + g) * 8 + 2 * t];

        float S[8][4];
        #pragma unroll
        for (int nt = 0; nt < 8; nt++) {
            S[nt][0] = 0.f; S[nt][1] = 0.f; S[nt][2] = 0.f; S[nt][3] = 0.f;
            MMA_F16K8(S[nt], aq, kb[nt]);
        }

        // row max (row g -> regs 0/1, row g+8 -> regs 2/3), quad reduce
        float m0 = -1e30f, m1 = -1e30f;
        #pragma unroll
        for (int nt = 0; nt < 8; nt++) {
            m0 = fmaxf(m0, fmaxf(S[nt][0], S[nt][1]));
            m1 = fmaxf(m1, fmaxf(S[nt][2], S[nt][3]));
        }
        m0 = fmaxf(m0, __shfl_xor_sync(0xffffffffu, m0, 1));
        m0 = fmaxf(m0, __shfl_xor_sync(0xffffffffu, m0, 2));
        m1 = fmaxf(m1, __shfl_xor_sync(0xffffffffu, m1, 1));
        m1 = fmaxf(m1, __shfl_xor_sync(0xffffffffu, m1, 2));

        float s0 = 0.f, s1 = 0.f;
        #pragma unroll
        for (int nt = 0; nt < 8; nt++) {
            S[nt][0] = __expf(S[nt][0] - m0);
            S[nt][1] = __expf(S[nt][1] - m0);
            S[nt][2] = __expf(S[nt][2] - m1);
            S[nt][3] = __expf(S[nt][3] - m1);
            s0 += S[nt][0] + S[nt][1];
            s1 += S[nt][2] + S[nt][3];
        }
        s0 += __shfl_xor_sync(0xffffffffu, s0, 1);
        s0 += __shfl_xor_sync(0xffffffffu, s0, 2);
        s1 += __shfl_xor_sync(0xffffffffu, s1, 1);
        s1 += __shfl_xor_sync(0xffffffffu, s1, 2);
        const float inv0 = 1.0f / s0;
        const float inv1 = 1.0f / s1;

        // O = P @ V : P A-frags come straight from S C-frags (f16 layout identity)
        float o[4] = {0.f, 0.f, 0.f, 0.f};
        #pragma unroll
        for (int q = 0; q < 4; q++) {
            uint32_t pa[4];
            pa[0] = packh2(S[2 * q][0], S[2 * q][1]);         // (row g,   k=16q+2t)
            pa[1] = packh2(S[2 * q][2], S[2 * q][3]);         // (row g+8, k=16q+2t)
            pa[2] = packh2(S[2 * q + 1][0], S[2 * q + 1][1]); // (row g,   k=16q+8+2t)
            pa[3] = packh2(S[2 * q + 1][2], S[2 * q + 1][3]); // (row g+8, k=16q+8+2t)
            MMA_F16(o, pa, vb[q]);
        }

        // store g_atth[px][qc*8+head]; heads 2t,2t+1 contiguous
        __half* ap = g_atth + base + (size_t)(mt * 16 + g) * 8 + 2 * t;
        *(__half2*)ap = __floats2half2_rn(o[0] * inv0, o[1] * inv0);
        *(__half2*)(ap + 64) = __floats2half2_rn(o[2] * inv1, o[3] * inv1);
    }
}

// ---------------------------------------------------------------------------
// 1x1 conv (Wu) + ReLU, f16 m16n8k16. BM=64 BN=64 BK=64; 256 threads.
// ---------------------------------------------------------------------------
__global__ __launch_bounds__(256) void wu_f16(float* __restrict__ out) {
    __shared__ __half As[2][64][72];   // [px][k]
    __shared__ __half Bs[2][64][72];   // [co][k]

    const int tid = threadIdx.x;
    const int warp = tid >> 5;
    const int lane = tid & 31;
    const int g = lane >> 2;
    const int t = lane & 3;

    const int px0 = blockIdx.x * 64;
    const int wm = (warp & 1) * 32;
    const int wn = (warp >> 1) * 16;

    float acc[2][2][4];
    #pragma unroll
    for (int mt = 0; mt < 2; mt++)
        #pragma unroll
        for (int nt = 0; nt < 2; nt++)
            #pragma unroll
            for (int r = 0; r < 4; r++) acc[mt][nt][r] = 0.f;

    auto fill = [&](int stage, int k0) {
        #pragma unroll
        for (int i = 0; i < 2; i++) {
            int id = i * 256 + tid;
            int row = id >> 3;
            int c = id & 7;
            cp_async16(&As[stage][row][c * 8], g_atth + (size_t)(px0 + row) * 512 + k0 + c * 8);
            cp_async16(&Bs[stage][row][c * 8], g_Wuh + (size_t)row * 512 + k0 + c * 8);
        }
        cp_commit();
    };

    fill(0, 0);
    fill(1, 64);

    for (int it = 0; it < 8; it++) {
        const int buf = it & 1;
        if (it == 7) cp_wait0(); else cp_wait1();
        __syncthreads();

        #pragma unroll
        for (int ks = 0; ks < 4; ks++) {
            const int kb = ks * 16;
            uint32_t af[2][4];
            #pragma unroll
            for (int mt = 0; mt < 2; mt++) {
                int m = wm + mt * 16 + g;
                af[mt][0] = *(const uint32_t*)&As[buf][m][kb + 2 * t];
                af[mt][1] = *(const uint32_t*)&As[buf][m + 8][kb + 2 * t];
                af[mt][2] = *(const uint32_t*)&As[buf][m][kb + 2 * t + 8];
                af[mt][3] = *(const uint32_t*)&As[buf][m + 8][kb + 2 * t + 8];
            }
            uint32_t bf[2][2];
            #pragma unroll
            for (int nt = 0; nt < 2; nt++) {
                int n = wn + nt * 8 + g;
                bf[nt][0] = *(const uint32_t*)&Bs[buf][n][kb + 2 * t];
                bf[nt][1] = *(const uint32_t*)&Bs[buf][n][kb + 2 * t + 8];
            }
            #pragma unroll
            for (int mt = 0; mt < 2; mt++)
                #pragma unroll
                for (int nt = 0; nt < 2; nt++)
                    MMA_F16(acc[mt][nt], af[mt], bf[nt]);
        }

        if (it + 2 < 8) {
            __syncthreads();
            fill(buf, (it + 2) * 64);
        }
    }

    const int b = px0 / HW;
    const int hwb = px0 - b * HW;
    #pragma unroll
    for (int mt = 0; mt < 2; mt++) {
        #pragma unroll
        for (int nt = 0; nt < 2; nt++) {
            int m0 = wm + mt * 16 + g;
            int n0 = wn + nt * 8 + 2 * t;
            float* o0 = out + ((size_t)(b * 64 + n0)) * HW + hwb;
            float* o1 = out + ((size_t)(b * 64 + n0 + 1)) * HW + hwb;
            o0[m0]     = fmaxf(acc[mt][nt][0], 0.f);
            o1[m0]     = fmaxf(acc[mt][nt][1], 0.f);
            o0[m0 + 8] = fmaxf(acc[mt][nt][2], 0.f);
            o1[m0 + 8] = fmaxf(acc[mt][nt][3], 0.f);
        }
    }
}

// ---------------------------------------------------------------------------
extern "C" void kernel_launch(void* const* d_in, const int* in_sizes, int n_in,
                              void* d_out, int out_size) {
    const float* x  = (const float*)d_in[0];
    const float* Wq = (const float*)d_in[1];
    const float* Wk = (const float*)d_in[2];
    const float* Wv = (const float*)d_in[3];
    const float* Wu = (const float*)d_in[4];
    float* out = (float*)d_out;

    prep_wh<<<(3 * 512 * KTOT + 255) / 256, 256>>>(Wq, Wk, Wv, Wu);
    im2colh<<<B_ * HDIM, 256>>>(x);
    conv_f16<<<dim3(NPX / 128, 4, 3), 128>>>();
    attn_f16<<<NPX / 8, 256>>>();
    wu_f16<<<NPX / 64, 256>>>(out);
}

// round 9
// speedup vs baseline: 8.4409x; 1.0404x over previous
#include <cuda_runtime.h>
#include <cuda_fp16.h>
#include <cstdint>

#define B_    8
#define CIN   64
#define HDIM  56
#define WDIM  56
#define HW    3136
#define NPX   25088
#define KTOT  576

// qkv: proj 0 (q) and 1 (k) in "t-layout" [px][c*8+head] (pre-scaled q);
//      proj 2 (v) natural [px][head*64+c]. All f16.
__device__ __half g_qkvh[3ull * NPX * 512];
__device__ __half g_atth[(unsigned long long)NPX * 512];   // [px][qc*8+head]
__device__ __half g_colh[(unsigned long long)NPX * KTOT];  // [px][k]
__device__ __half g_Wth[3ull * 512 * KTOT];                // [proj][row][k]
__device__ __half g_Wuh[64 * 512];                         // [co][k]

__device__ __forceinline__ void cp_async16(void* smem, const void* gmem) {
    unsigned saddr = (unsigned)__cvta_generic_to_shared(smem);
    asm volatile("cp.async.cg.shared.global [%0], [%1], 16;" :: "r"(saddr), "l"(gmem));
}
__device__ __forceinline__ void cp_commit() { asm volatile("cp.async.commit_group;"); }
__device__ __forceinline__ void cp_wait0() { asm volatile("cp.async.wait_group 0;"); }
__device__ __forceinline__ void cp_wait1() { asm volatile("cp.async.wait_group 1;"); }

__device__ __forceinline__ void ldsm_x4(uint32_t* r, uint32_t saddr) {
    asm volatile("ldmatrix.sync.aligned.m8n8.x4.shared.b16 {%0,%1,%2,%3}, [%4];"
                 : "=r"(r[0]), "=r"(r[1]), "=r"(r[2]), "=r"(r[3]) : "r"(saddr));
}

// f16 mma m16n8k16, fp32 accumulate
#define MMA_F16(acc, a, b)                                                      \
    asm volatile(                                                               \
        "mma.sync.aligned.m16n8k16.row.col.f32.f16.f16.f32 "                    \
        "{%0,%1,%2,%3}, {%4,%5,%6,%7}, {%8,%9}, {%0,%1,%2,%3};"                 \
        : "+f"((acc)[0]), "+f"((acc)[1]), "+f"((acc)[2]), "+f"((acc)[3])        \
        : "r"((a)[0]), "r"((a)[1]), "r"((a)[2]), "r"((a)[3]),                   \
          "r"((b)[0]), "r"((b)[1]))

// f16 mma m16n8k8, fp32 accumulate
#define MMA_F16K8(acc, a, b)                                                    \
    asm volatile(                                                               \
        "mma.sync.aligned.m16n8k8.row.col.f32.f16.f16.f32 "                     \
        "{%0,%1,%2,%3}, {%4,%5}, {%6}, {%0,%1,%2,%3};"                          \
        : "+f"((acc)[0]), "+f"((acc)[1]), "+f"((acc)[2]), "+f"((acc)[3])        \
        : "r"((a)[0]), "r"((a)[1]), "r"(b))

__device__ __forceinline__ uint32_t packh2(float lo, float hi) {
    __half2 h = __floats2half2_rn(lo, hi);
    return *(uint32_t*)&h;
}

// ---------------------------------------------------------------------------
// Weight prep. q/k rows permuted to t-layout; 1/sqrt(512) folded into Wq.
// ---------------------------------------------------------------------------
__global__ void prep_wh(const float* __restrict__ Wq, const float* __restrict__ Wk,
                        const float* __restrict__ Wv, const float* __restrict__ Wu) {
    int idx = blockIdx.x * blockDim.x + threadIdx.x;
    const int tot = 3 * 512 * KTOT;
    if (idx < tot) {
        int k = idx % KTOT;
        int r = (idx / KTOT) & 511;
        int proj = idx / (KTOT * 512);
        int tap = k >> 6;
        int ic = k & 63;
        int oc = (proj < 2) ? ((r & 7) * 64 + (r >> 3)) : r;
        const float* src = (proj == 0) ? Wq : ((proj == 1) ? Wk : Wv);
        float w = src[(oc * 64 + ic) * 9 + tap];
        if (proj == 0) w *= 0.04419417382415922f;   // 1/sqrt(512)
        g_Wth[idx] = __float2half_rn(w);
    }
    if (idx < 64 * 512) {
        g_Wuh[idx] = __float2half_rn(Wu[idx]);
    }
}

// ---------------------------------------------------------------------------
// im2col f16, K-major: g_colh[px][576]. One block per (b, h) image row.
// ---------------------------------------------------------------------------
__global__ __launch_bounds__(256) void im2colh(const float* __restrict__ x) {
    __shared__ float xs[64][3][61];
    const int b = blockIdx.x / HDIM;
    const int h = blockIdx.x % HDIM;
    const int tid = threadIdx.x;

    for (int i = tid; i < 64 * 3 * 61; i += 256)
        ((float*)xs)[i] = 0.f;
    __syncthreads();

    #pragma unroll
    for (int r = 0; r < 3; r++) {
        const int hh = h - 1 + r;
        if (hh >= 0 && hh < HDIM) {
            for (int i = tid; i < 64 * 56; i += 256) {
                int ic = i / 56;
                int w = i - ic * 56;
                xs[ic][r][1 + w] = x[((size_t)(b * CIN + ic)) * HW + hh * WDIM + w];
            }
        }
    }
    __syncthreads();

    __half* outb = g_colh + ((size_t)(b * HW + h * WDIM)) * KTOT;
    for (int i = tid; i < 56 * KTOT; i += 256) {
        int w = i / KTOT;
        int k = i - w * KTOT;
        int tap = k >> 6;
        int ic = k & 63;
        int dr = tap / 3;
        int dc = tap % 3;
        outb[(size_t)w * KTOT + k] = __float2half_rn(xs[ic][dr][w + dc]);
    }
}

// ---------------------------------------------------------------------------
// qkv conv GEMM, f16 m16n8k16, ldmatrix fragment loads, 2-stage pipeline.
// BM=128 BN=128 BK=32; 128 threads (2x2 warps), warp tile 64x64.
// ---------------------------------------------------------------------------
#define NITER 18
#define ASTR 40

__global__ __launch_bounds__(128) void conv_f16() {
    __shared__ __half As[2][128][ASTR];   // [px][k]
    __shared__ __half Bs[2][128][ASTR];   // [row][k]

    const int tid = threadIdx.x;
    const int warp = tid >> 5;
    const int lane = tid & 31;
    const int g = lane >> 2;
    const int t = lane & 3;

    const int px0 = blockIdx.x * 128;
    const int oc0 = blockIdx.y * 128;
    const int proj = blockIdx.z;
    const int warpM = (warp & 1) * 64;
    const int warpN = (warp >> 1) * 64;

    const __half* asrc = g_colh + (size_t)px0 * KTOT;
    const __half* bsrc = g_Wth + ((size_t)proj * 512 + oc0) * KTOT;

    // ldmatrix per-lane offsets
    const int lr = lane & 7;
    const int a_row = lr + 8 * ((lane >> 3) & 1);   // row within 16-row tile
    const int a_col = 8 * ((lane >> 4) & 1);        // k 8-block
    const int b_row = lr + 8 * ((lane >> 4) & 1);
    const int b_col = 8 * ((lane >> 3) & 1);

    const uint32_t sA = (uint32_t)__cvta_generic_to_shared(&As[0][0][0]);
    const uint32_t sB = (uint32_t)__cvta_generic_to_shared(&Bs[0][0][0]);
    const uint32_t bufstep = 128 * ASTR * 2;

    float acc[4][8][4];
    #pragma unroll
    for (int mt = 0; mt < 4; mt++)
        #pragma unroll
        for (int nt = 0; nt < 8; nt++)
            #pragma unroll
            for (int r = 0; r < 4; r++) acc[mt][nt][r] = 0.f;

    auto fill = [&](int buf, int kk) {
        const int kof = kk * 32;
        #pragma unroll
        for (int i = 0; i < 4; i++) {
            int id = i * 128 + tid;
            int row = id >> 2;
            int c = id & 3;
            cp_async16(&As[buf][row][c * 8], asrc + (size_t)row * KTOT + kof + c * 8);
            cp_async16(&Bs[buf][row][c * 8], bsrc + (size_t)row * KTOT + kof + c * 8);
        }
        cp_commit();
    };

    fill(0, 0);
    fill(1, 1);

    for (int kk = 0; kk < NITER; kk++) {
        const int buf = kk & 1;
        if (kk == NITER - 1) cp_wait0(); else cp_wait1();
        __syncthreads();

        const uint32_t aBase = sA + buf * bufstep;
        const uint32_t bBase = sB + buf * bufstep;

        #pragma unroll
        for (int ks = 0; ks < 2; ks++) {
            const int kb = ks * 16;
            uint32_t af[4][4];
            #pragma unroll
            for (int mt = 0; mt < 4; mt++)
                ldsm_x4(af[mt], aBase + ((warpM + mt * 16 + a_row) * ASTR + kb + a_col) * 2);
            uint32_t bf[8][2];
            #pragma unroll
            for (int ntp = 0; ntp < 4; ntp++) {
                uint32_t tmp[4];
                ldsm_x4(tmp, bBase + ((warpN + ntp * 16 + b_row) * ASTR + kb + b_col) * 2);
                bf[2 * ntp][0] = tmp[0];
                bf[2 * ntp][1] = tmp[1];
                bf[2 * ntp + 1][0] = tmp[2];
                bf[2 * ntp + 1][1] = tmp[3];
            }
            #pragma unroll
            for (int mt = 0; mt < 4; mt++)
                #pragma unroll
                for (int nt = 0; nt < 8; nt++)
                    MMA_F16(acc[mt][nt], af[mt], bf[nt]);
        }

        if (kk + 2 < NITER) {
            __syncthreads();
            fill(buf, kk + 2);
        }
    }

    __half* outp = g_qkvh + (size_t)proj * NPX * 512;
    #pragma unroll
    for (int mt = 0; mt < 4; mt++) {
        #pragma unroll
        for (int nt = 0; nt < 8; nt++) {
            int r0 = px0 + warpM + mt * 16 + g;
            int c0 = oc0 + warpN + nt * 8 + 2 * t;
            *(__half2*)(outp + (size_t)r0 * 512 + c0) =
                __floats2half2_rn(acc[mt][nt][0], acc[mt][nt][1]);
            *(__half2*)(outp + (size_t)(r0 + 8) * 512 + c0) =
                __floats2half2_rn(acc[mt][nt][2], acc[mt][nt][3]);
        }
    }
}

// ---------------------------------------------------------------------------
// f16 tensor-core attention, zero-shuffle P transpose (round-7 proven).
// ---------------------------------------------------------------------------
__global__ __launch_bounds__(256) void attn_f16() {
    const int warp = threadIdx.x >> 5;
    const int lane = threadIdx.x & 31;
    const int g = lane >> 2;
    const int t = lane & 3;
    const int p = blockIdx.x * 8 + warp;
    const size_t base = (size_t)p * 512;
    const __half* qp = g_qkvh + base;
    const __half* kp = g_qkvh + (size_t)NPX * 512 + base;
    const __half* vp = g_qkvh + 2ull * NPX * 512 + base;

    uint32_t kb[8];
    #pragma unroll
    for (int nt = 0; nt < 8; nt++)
        kb[nt] = *(const uint32_t*)&kp[(nt * 8 + g) * 8 + 2 * t];

    uint32_t vb[4][2];
    #pragma unroll
    for (int q = 0; q < 4; q++) {
        vb[q][0] = *(const uint32_t*)&vp[g * 64 + 16 * q + 2 * t];
        vb[q][1] = *(const uint32_t*)&vp[g * 64 + 16 * q + 8 + 2 * t];
    }

    #pragma unroll
    for (int mt = 0; mt < 4; mt++) {
        uint32_t aq[2];
        aq[0] = *(const uint32_t*)&qp[(mt * 16 + g) * 8 + 2 * t];
        aq[1] = *(const uint32_t*)&qp[(mt * 16 + 8 + g) * 8 + 2 * t];

        float S[8][4];
        #pragma unroll
        for (int nt = 0; nt < 8; nt++) {
            S[nt][0] = 0.f; S[nt][1] = 0.f; S[nt][2] = 0.f; S[nt][3] = 0.f;
            MMA_F16K8(S[nt], aq, kb[nt]);
        }

        float m0 = -1e30f, m1 = -1e30f;
        #pragma unroll
        for (int nt = 0; nt < 8; nt++) {
            m0 = fmaxf(m0, fmaxf(S[nt][0], S[nt][1]));
            m1 = fmaxf(m1, fmaxf(S[nt][2], S[nt][3]));
        }
        m0 = fmaxf(m0, __shfl_xor_sync(0xffffffffu, m0, 1));
        m0 = fmaxf(m0, __shfl_xor_sync(0xffffffffu, m0, 2));
        m1 = fmaxf(m1, __shfl_xor_sync(0xffffffffu, m1, 1));
        m1 = fmaxf(m1, __shfl_xor_sync(0xffffffffu, m1, 2));

        float s0 = 0.f, s1 = 0.f;
        #pragma unroll
        for (int nt = 0; nt < 8; nt++) {
            S[nt][0] = __expf(S[nt][0] - m0);
            S[nt][1] = __expf(S[nt][1] - m0);
            S[nt][2] = __expf(S[nt][2] - m1);
            S[nt][3] = __expf(S[nt][3] - m1);
            s0 += S[nt][0] + S[nt][1];
            s1 += S[nt][2] + S[nt][3];
        }
        s0 += __shfl_xor_sync(0xffffffffu, s0, 1);
        s0 += __shfl_xor_sync(0xffffffffu, s0, 2);
        s1 += __shfl_xor_sync(0xffffffffu, s1, 1);
        s1 += __shfl_xor_sync(0xffffffffu, s1, 2);
        const float inv0 = 1.0f / s0;
        const float inv1 = 1.0f / s1;

        float o[4] = {0.f, 0.f, 0.f, 0.f};
        #pragma unroll
        for (int q = 0; q < 4; q++) {
            uint32_t pa[4];
            pa[0] = packh2(S[2 * q][0], S[2 * q][1]);
            pa[1] = packh2(S[2 * q][2], S[2 * q][3]);
            pa[2] = packh2(S[2 * q + 1][0], S[2 * q + 1][1]);
            pa[3] = packh2(S[2 * q + 1][2], S[2 * q + 1][3]);
            MMA_F16(o, pa, vb[q]);
        }

        __half* ap = g_atth + base + (size_t)(mt * 16 + g) * 8 + 2 * t;
        *(__half2*)ap = __floats2half2_rn(o[0] * inv0, o[1] * inv0);
        *(__half2*)(ap + 64) = __floats2half2_rn(o[2] * inv1, o[3] * inv1);
    }
}

// ---------------------------------------------------------------------------
// 1x1 conv (Wu) + ReLU, f16 m16n8k16 + ldmatrix. BM=64 BN=64 BK=64.
// ---------------------------------------------------------------------------
#define WSTR 72

__global__ __launch_bounds__(256) void wu_f16(float* __restrict__ out) {
    __shared__ __half As[2][64][WSTR];   // [px][k]
    __shared__ __half Bs[2][64][WSTR];   // [co][k]

    const int tid = threadIdx.x;
    const int warp = tid >> 5;
    const int lane = tid & 31;
    const int g = lane >> 2;
    const int t = lane & 3;

    const int px0 = blockIdx.x * 64;
    const int wm = (warp & 1) * 32;
    const int wn = (warp >> 1) * 16;

    const int lr = lane & 7;
    const int a_row = lr + 8 * ((lane >> 3) & 1);
    const int a_col = 8 * ((lane >> 4) & 1);
    const int b_row = lr + 8 * ((lane >> 4) & 1);
    const int b_col = 8 * ((lane >> 3) & 1);

    const uint32_t sA = (uint32_t)__cvta_generic_to_shared(&As[0][0][0]);
    const uint32_t sB = (uint32_t)__cvta_generic_to_shared(&Bs[0][0][0]);
    const uint32_t bufstep = 64 * WSTR * 2;

    float acc[2][2][4];
    #pragma unroll
    for (int mt = 0; mt < 2; mt++)
        #pragma unroll
        for (int nt = 0; nt < 2; nt++)
            #pragma unroll
            for (int r = 0; r < 4; r++) acc[mt][nt][r] = 0.f;

    auto fill = [&](int stage, int k0) {
        #pragma unroll
        for (int i = 0; i < 2; i++) {
            int id = i * 256 + tid;
            int row = id >> 3;
            int c = id & 7;
            cp_async16(&As[stage][row][c * 8], g_atth + (size_t)(px0 + row) * 512 + k0 + c * 8);
            cp_async16(&Bs[stage][row][c * 8], g_Wuh + (size_t)row * 512 + k0 + c * 8);
        }
        cp_commit();
    };

    fill(0, 0);
    fill(1, 64);

    for (int it = 0; it < 8; it++) {
        const int buf = it & 1;
        if (it == 7) cp_wait0(); else cp_wait1();
        __syncthreads();

        const uint32_t aBase = sA + buf * bufstep;
        const uint32_t bBase = sB + buf * bufstep;

        #pragma unroll
        for (int ks = 0; ks < 4; ks++) {
            const int kb = ks * 16;
            uint32_t af[2][4];
            #pragma unroll
            for (int mt = 0; mt < 2; mt++)
                ldsm_x4(af[mt], aBase + ((wm + mt * 16 + a_row) * WSTR + kb + a_col) * 2);
            uint32_t bf[2][2];
            {
                uint32_t tmp[4];
                ldsm_x4(tmp, bBase + ((wn + b_row) * WSTR + kb + b_col) * 2);
                bf[0][0] = tmp[0];
                bf[0][1] = tmp[1];
                bf[1][0] = tmp[2];
                bf[1][1] = tmp[3];
            }
            #pragma unroll
            for (int mt = 0; mt < 2; mt++)
                #pragma unroll
                for (int nt = 0; nt < 2; nt++)
                    MMA_F16(acc[mt][nt], af[mt], bf[nt]);
        }

        if (it + 2 < 8) {
            __syncthreads();
            fill(buf, (it + 2) * 64);
        }
    }

    const int b = px0 / HW;
    const int hwb = px0 - b * HW;
    #pragma unroll
    for (int mt = 0; mt < 2; mt++) {
        #pragma unroll
        for (int nt = 0; nt < 2; nt++) {
            int m0 = wm + mt * 16 + g;
            int n0 = wn + nt * 8 + 2 * t;
            float* o0 = out + ((size_t)(b * 64 + n0)) * HW + hwb;
            float* o1 = out + ((size_t)(b * 64 + n0 + 1)) * HW + hwb;
            o0[m0]     = fmaxf(acc[mt][nt][0], 0.f);
            o1[m0]     = fmaxf(acc[mt][nt][1], 0.f);
            o0[m0 + 8] = fmaxf(acc[mt][nt][2], 0.f);
            o1[m0 + 8] = fmaxf(acc[mt][nt][3], 0.f);
        }
    }
}

// ---------------------------------------------------------------------------
extern "C" void kernel_launch(void* const* d_in, const int* in_sizes, int n_in,
                              void* d_out, int out_size) {
    const float* x  = (const float*)d_in[0];
    const float* Wq = (const float*)d_in[1];
    const float* Wk = (const float*)d_in[2];
    const float* Wv = (const float*)d_in[3];
    const float* Wu = (const float*)d_in[4];
    float* out = (float*)d_out;

    prep_wh<<<(3 * 512 * KTOT + 255) / 256, 256>>>(Wq, Wk, Wv, Wu);
    im2colh<<<B_ * HDIM, 256>>>(x);
    conv_f16<<<dim3(NPX / 128, 4, 3), 128>>>();
    attn_f16<<<NPX / 8, 256>>>();
    wu_f16<<<NPX / 64, 256>>>(out);
}